// round 1
// baseline (speedup 1.0000x reference)
#include <cuda_runtime.h>
#include <math.h>

#define B_   2
#define S_   2048
#define D_   1024
#define H_   16
#define DH_  64
#define NT_  (B_ * S_)          // 4096 tokens

// Scratch (allocation-free rule -> __device__ globals)
__device__ float g_q[NT_ * D_];
__device__ float g_k[NT_ * D_];
__device__ float g_v[NT_ * D_];
__device__ float g_att[NT_ * D_];

// ---------------------------------------------------------------------------
// C[M,N] = A[M,K] @ W[N,K]^T   (both operands K-contiguous row-major)
// 64x64 tile, BK=32, 256 threads, 4x4 register micro-tile.
// ---------------------------------------------------------------------------
__global__ __launch_bounds__(256) void gemm_nt_kernel(
    const float* __restrict__ A, const float* __restrict__ W,
    float* __restrict__ C, int M, int N, int K)
{
    const int BK = 32, PAD = 68;
    __shared__ float As[BK][PAD];   // [k][m] transposed
    __shared__ float Bs[BK][PAD];   // [k][n] transposed

    int tid = threadIdx.x;
    int tx = tid & 15;          // 0..15 -> n
    int ty = tid >> 4;          // 0..15 -> m
    int m0 = blockIdx.y * 64;
    int n0 = blockIdx.x * 64;

    float acc[4][4] = {};

    for (int k0 = 0; k0 < K; k0 += BK) {
        #pragma unroll
        for (int u = 0; u < 2; u++) {
            int t2  = tid * 2 + u;          // 0..511
            int row = t2 >> 3;              // 0..63
            int kq  = (t2 & 7) * 4;         // 0..28
            float4 a = *(const float4*)&A[(size_t)(m0 + row) * K + k0 + kq];
            As[kq + 0][row] = a.x; As[kq + 1][row] = a.y;
            As[kq + 2][row] = a.z; As[kq + 3][row] = a.w;
            float4 b = *(const float4*)&W[(size_t)(n0 + row) * K + k0 + kq];
            Bs[kq + 0][row] = b.x; Bs[kq + 1][row] = b.y;
            Bs[kq + 2][row] = b.z; Bs[kq + 3][row] = b.w;
        }
        __syncthreads();

        #pragma unroll
        for (int kk = 0; kk < BK; kk++) {
            float4 a4 = *(const float4*)&As[kk][ty * 4];
            float4 b4 = *(const float4*)&Bs[kk][tx * 4];
            float av[4] = {a4.x, a4.y, a4.z, a4.w};
            float bv[4] = {b4.x, b4.y, b4.z, b4.w};
            #pragma unroll
            for (int i = 0; i < 4; i++)
                #pragma unroll
                for (int j = 0; j < 4; j++)
                    acc[i][j] = fmaf(av[i], bv[j], acc[i][j]);
        }
        __syncthreads();
    }

    #pragma unroll
    for (int i = 0; i < 4; i++) {
        float4 o = {acc[i][0], acc[i][1], acc[i][2], acc[i][3]};
        *(float4*)&C[(size_t)(m0 + ty * 4 + i) * N + n0 + tx * 4] = o;
    }
}

// ---------------------------------------------------------------------------
// Causal flash attention, fp32.
// One block per (q-tile of 64, head, batch). 256 threads, 4x4 micro-tile.
// Online softmax state (m, l, rescale) in smem; O accumulator in registers.
// ---------------------------------------------------------------------------
__global__ __launch_bounds__(256) void attn_kernel(
    const float* __restrict__ q, const float* __restrict__ k,
    const float* __restrict__ v, float* __restrict__ att)
{
    const int PAD = 68;
    extern __shared__ float sm[];
    float* Qs   = sm;                  // 64 x 68
    float* Ks   = Qs + 64 * PAD;
    float* Vs   = Ks + 64 * PAD;
    float* Ss   = Vs + 64 * PAD;
    float* mrow = Ss + 64 * PAD;       // 64
    float* lrow = mrow + 64;           // 64
    float* srow = lrow + 64;           // 64 (per-round rescale)

    int tid = threadIdx.x;
    int tx = tid & 15;      // key/out col group
    int ty = tid >> 4;      // query row group
    int qt = blockIdx.x;    // 0..31
    int h  = blockIdx.y;    // 0..15
    int b  = blockIdx.z;    // 0..1

    const float scale = 0.125f;  // 1/sqrt(64)

    // Load Q tile (pre-scaled)
    const float* qbase = q + ((size_t)(b * S_ + qt * 64)) * D_ + h * DH_;
    for (int i = tid; i < 64 * 16; i += 256) {
        int r = i >> 4, c4 = (i & 15) * 4;
        float4 t = *(const float4*)&qbase[(size_t)r * D_ + c4];
        Qs[r * PAD + c4 + 0] = t.x * scale;
        Qs[r * PAD + c4 + 1] = t.y * scale;
        Qs[r * PAD + c4 + 2] = t.z * scale;
        Qs[r * PAD + c4 + 3] = t.w * scale;
    }
    if (tid < 64) { mrow[tid] = -1e30f; lrow[tid] = 0.0f; }

    float acc[4][4] = {};

    for (int kt = 0; kt <= qt; kt++) {
        __syncthreads();  // prev-iter consumers of Ks/Vs done; Q/m/l visible
        const float* kbase = k + ((size_t)(b * S_ + kt * 64)) * D_ + h * DH_;
        const float* vbase = v + ((size_t)(b * S_ + kt * 64)) * D_ + h * DH_;
        for (int i = tid; i < 64 * 16; i += 256) {
            int r = i >> 4, c4 = (i & 15) * 4;
            float4 tk = *(const float4*)&kbase[(size_t)r * D_ + c4];
            Ks[r * PAD + c4 + 0] = tk.x; Ks[r * PAD + c4 + 1] = tk.y;
            Ks[r * PAD + c4 + 2] = tk.z; Ks[r * PAD + c4 + 3] = tk.w;
            float4 tv = *(const float4*)&vbase[(size_t)r * D_ + c4];
            Vs[r * PAD + c4 + 0] = tv.x; Vs[r * PAD + c4 + 1] = tv.y;
            Vs[r * PAD + c4 + 2] = tv.z; Vs[r * PAD + c4 + 3] = tv.w;
        }
        __syncthreads();

        // S = Q K^T (per-thread 4x4)
        bool diag = (kt == qt);
        float sc[4][4] = {};
        #pragma unroll 4
        for (int kk = 0; kk < 64; kk++) {
            float av[4], bv[4];
            #pragma unroll
            for (int i = 0; i < 4; i++) av[i] = Qs[(ty * 4 + i) * PAD + kk];
            #pragma unroll
            for (int j = 0; j < 4; j++) bv[j] = Ks[(tx * 4 + j) * PAD + kk];
            #pragma unroll
            for (int i = 0; i < 4; i++)
                #pragma unroll
                for (int j = 0; j < 4; j++)
                    sc[i][j] = fmaf(av[i], bv[j], sc[i][j]);
        }
        #pragma unroll
        for (int i = 0; i < 4; i++)
            #pragma unroll
            for (int j = 0; j < 4; j++) {
                int r = ty * 4 + i, c = tx * 4 + j;
                if (diag && c > r) sc[i][j] = -1e30f;
                Ss[r * PAD + c] = sc[i][j];
            }
        __syncthreads();

        // Online softmax update (one thread per query row)
        if (tid < 64) {
            int r = tid;
            float rm = -1e30f;
            for (int c = 0; c < 64; c++) rm = fmaxf(rm, Ss[r * PAD + c]);
            float nm   = fmaxf(mrow[r], rm);
            float corr = __expf(mrow[r] - nm);
            float sum  = 0.0f;
            for (int c = 0; c < 64; c++) {
                float p = __expf(Ss[r * PAD + c] - nm);
                Ss[r * PAD + c] = p;
                sum += p;
            }
            lrow[r] = lrow[r] * corr + sum;
            mrow[r] = nm;
            srow[r] = corr;
        }
        __syncthreads();

        // O = O*corr + P @ V
        #pragma unroll
        for (int i = 0; i < 4; i++) {
            float cr = srow[ty * 4 + i];
            #pragma unroll
            for (int j = 0; j < 4; j++) acc[i][j] *= cr;
        }
        #pragma unroll 4
        for (int c = 0; c < 64; c++) {
            float pv[4], vv[4];
            #pragma unroll
            for (int i = 0; i < 4; i++) pv[i] = Ss[(ty * 4 + i) * PAD + c];
            #pragma unroll
            for (int j = 0; j < 4; j++) vv[j] = Vs[c * PAD + tx * 4 + j];
            #pragma unroll
            for (int i = 0; i < 4; i++)
                #pragma unroll
                for (int j = 0; j < 4; j++)
                    acc[i][j] = fmaf(pv[i], vv[j], acc[i][j]);
        }
    }

    // Normalize and write [B, S, H*Dh] layout
    float* obase = att + ((size_t)(b * S_ + qt * 64)) * D_ + h * DH_;
    #pragma unroll
    for (int i = 0; i < 4; i++) {
        float inv = 1.0f / lrow[ty * 4 + i];
        float4 o = {acc[i][0] * inv, acc[i][1] * inv,
                    acc[i][2] * inv, acc[i][3] * inv};
        *(float4*)&obase[(size_t)(ty * 4 + i) * D_ + tx * 4] = o;
    }
}

// ---------------------------------------------------------------------------

extern "C" void kernel_launch(void* const* d_in, const int* in_sizes, int n_in,
                              void* d_out, int out_size)
{
    const float* x  = (const float*)d_in[0];
    const float* wq = (const float*)d_in[1];
    const float* wk = (const float*)d_in[2];
    const float* wv = (const float*)d_in[3];
    const float* wo = (const float*)d_in[4];
    float* out = (float*)d_out;

    float *q, *k, *v, *att;
    cudaGetSymbolAddress((void**)&q,   g_q);
    cudaGetSymbolAddress((void**)&k,   g_k);
    cudaGetSymbolAddress((void**)&v,   g_v);
    cudaGetSymbolAddress((void**)&att, g_att);

    dim3 gg(D_ / 64, NT_ / 64);     // (16, 64)
    gemm_nt_kernel<<<gg, 256>>>(x, wq, q, NT_, D_, D_);
    gemm_nt_kernel<<<gg, 256>>>(x, wk, k, NT_, D_, D_);
    gemm_nt_kernel<<<gg, 256>>>(x, wv, v, NT_, D_, D_);

    int smem = (4 * 64 * 68 + 3 * 64) * (int)sizeof(float);  // 70400 B
    cudaFuncSetAttribute(attn_kernel,
                         cudaFuncAttributeMaxDynamicSharedMemorySize, smem);
    dim3 ga(S_ / 64, H_, B_);       // (32, 16, 2)
    attn_kernel<<<ga, 256, smem>>>(q, k, v, att);

    gemm_nt_kernel<<<gg, 256>>>(att, wo, out, NT_, D_, D_);
}

// round 2
// speedup vs baseline: 1.4912x; 1.4912x over previous
#include <cuda_runtime.h>
#include <math.h>

#define B_   2
#define S_   2048
#define D_   1024
#define H_   16
#define DH_  64
#define NT_  (B_ * S_)          // 4096 tokens

// Scratch (allocation-free rule -> __device__ globals)
__device__ float g_q[NT_ * D_];
__device__ float g_k[NT_ * D_];
__device__ float g_v[NT_ * D_];
__device__ float g_att[NT_ * D_];

// ---------------------------------------------------------------------------
// C[M,N] = A[M,K] @ W[N,K]^T   (both operands K-contiguous row-major)
// 128x128 tile, BK=16, 256 threads, 8x8 register micro-tile (4+4 split),
// register prefetch of the next K-slab.
// ---------------------------------------------------------------------------
__global__ __launch_bounds__(256, 2) void gemm_nt_kernel(
    const float* __restrict__ A, const float* __restrict__ W,
    float* __restrict__ C, int M, int N, int K)
{
    const int PG = 132;                 // 128 + 4 pad (pitch in floats)
    __shared__ float As[16 * PG];       // [k][m]
    __shared__ float Bs[16 * PG];       // [k][n]

    int tid = threadIdx.x;
    int tx = tid & 15;                  // n group
    int ty = tid >> 4;                  // m group
    int m0 = blockIdx.y * 128;
    int n0 = blockIdx.x * 128;

    int lr = tid >> 2;                  // 0..63 (row within half-tile)
    int lk = (tid & 3) * 4;             // 0,4,8,12
    const float* Ap = A + (size_t)(m0 + lr) * K + lk;
    const float* Wp = W + (size_t)(n0 + lr) * K + lk;
    size_t half = (size_t)64 * K;

    float4 pa0 = *(const float4*)&Ap[0];
    float4 pa1 = *(const float4*)&Ap[half];
    float4 pb0 = *(const float4*)&Wp[0];
    float4 pb1 = *(const float4*)&Wp[half];

    float acc[8][8] = {};

    for (int k0 = 0; k0 < K; k0 += 16) {
        // commit prefetched slab to smem (transposed)
        As[(lk + 0) * PG + lr] = pa0.x; As[(lk + 1) * PG + lr] = pa0.y;
        As[(lk + 2) * PG + lr] = pa0.z; As[(lk + 3) * PG + lr] = pa0.w;
        As[(lk + 0) * PG + lr + 64] = pa1.x; As[(lk + 1) * PG + lr + 64] = pa1.y;
        As[(lk + 2) * PG + lr + 64] = pa1.z; As[(lk + 3) * PG + lr + 64] = pa1.w;
        Bs[(lk + 0) * PG + lr] = pb0.x; Bs[(lk + 1) * PG + lr] = pb0.y;
        Bs[(lk + 2) * PG + lr] = pb0.z; Bs[(lk + 3) * PG + lr] = pb0.w;
        Bs[(lk + 0) * PG + lr + 64] = pb1.x; Bs[(lk + 1) * PG + lr + 64] = pb1.y;
        Bs[(lk + 2) * PG + lr + 64] = pb1.z; Bs[(lk + 3) * PG + lr + 64] = pb1.w;
        __syncthreads();

        if (k0 + 16 < K) {
            pa0 = *(const float4*)&Ap[k0 + 16];
            pa1 = *(const float4*)&Ap[half + k0 + 16];
            pb0 = *(const float4*)&Wp[k0 + 16];
            pb1 = *(const float4*)&Wp[half + k0 + 16];
        }

        #pragma unroll
        for (int kk = 0; kk < 16; kk++) {
            float4 a0 = *(const float4*)&As[kk * PG + ty * 4];
            float4 a1 = *(const float4*)&As[kk * PG + 64 + ty * 4];
            float4 b0 = *(const float4*)&Bs[kk * PG + tx * 4];
            float4 b1 = *(const float4*)&Bs[kk * PG + 64 + tx * 4];
            float av[8] = {a0.x, a0.y, a0.z, a0.w, a1.x, a1.y, a1.z, a1.w};
            float bv[8] = {b0.x, b0.y, b0.z, b0.w, b1.x, b1.y, b1.z, b1.w};
            #pragma unroll
            for (int i = 0; i < 8; i++)
                #pragma unroll
                for (int j = 0; j < 8; j++)
                    acc[i][j] = fmaf(av[i], bv[j], acc[i][j]);
        }
        __syncthreads();
    }

    #pragma unroll
    for (int i = 0; i < 8; i++) {
        int mr = m0 + ((i < 4) ? (ty * 4 + i) : (64 + ty * 4 + i - 4));
        float4 o0 = {acc[i][0], acc[i][1], acc[i][2], acc[i][3]};
        float4 o1 = {acc[i][4], acc[i][5], acc[i][6], acc[i][7]};
        *(float4*)&C[(size_t)mr * N + n0 + tx * 4] = o0;
        *(float4*)&C[(size_t)mr * N + n0 + 64 + tx * 4] = o1;
    }
}

// ---------------------------------------------------------------------------
// Causal flash attention, fp32. One block per (64-row q-tile, head, batch).
// Q,K stored transposed [k][row] in smem (conflict-free float4 frag loads);
// S row-major with conflict-free float4 stores; softmax 4 threads/row.
// ---------------------------------------------------------------------------
__global__ __launch_bounds__(256) void attn_kernel(
    const float* __restrict__ q, const float* __restrict__ k,
    const float* __restrict__ v, float* __restrict__ att)
{
    const int P = 68;
    extern __shared__ float sm[];
    float* Qs   = sm;                  // [64 k][68]  (transposed: Qs[kk*P + r])
    float* Ks   = Qs + 64 * P;         // [64 k][68]  (transposed: Ks[kk*P + c])
    float* Vs   = Ks + 64 * P;         // [64 c][68]  (row-major:  Vs[c*P + d])
    float* Ss   = Vs + 64 * P;         // [64 r][68]  (row-major:  Ss[r*P + c])
    float* mrow = Ss + 64 * P;         // 64
    float* lrow = mrow + 64;           // 64
    float* srow = lrow + 64;           // 64 (per-round rescale)

    int tid = threadIdx.x;
    int tx = tid & 15;      // key/out col group
    int ty = tid >> 4;      // query row group
    int qt = blockIdx.x;    // 0..31
    int h  = blockIdx.y;    // 0..15
    int b  = blockIdx.z;    // 0..1

    const float scale = 0.125f;  // 1/sqrt(64)

    // Load Q tile transposed (row-fast mapping: strided global, conflict-free
    // smem stores), pre-scaled.
    const float* qbase = q + ((size_t)(b * S_ + qt * 64)) * D_ + h * DH_;
    for (int i = tid; i < 64 * 16; i += 256) {
        int r = i & 63, k4 = (i >> 6) * 4;
        float4 t = *(const float4*)&qbase[(size_t)r * D_ + k4];
        Qs[(k4 + 0) * P + r] = t.x * scale;
        Qs[(k4 + 1) * P + r] = t.y * scale;
        Qs[(k4 + 2) * P + r] = t.z * scale;
        Qs[(k4 + 3) * P + r] = t.w * scale;
    }
    if (tid < 64) { mrow[tid] = -1e30f; lrow[tid] = 0.0f; }

    float acc[4][4] = {};

    for (int kt = 0; kt <= qt; kt++) {
        __syncthreads();  // prev-iter consumers of Ks/Vs/Ss done
        const float* kbase = k + ((size_t)(b * S_ + kt * 64)) * D_ + h * DH_;
        const float* vbase = v + ((size_t)(b * S_ + kt * 64)) * D_ + h * DH_;
        for (int i = tid; i < 64 * 16; i += 256) {
            int c = i & 63, k4 = (i >> 6) * 4;
            float4 t = *(const float4*)&kbase[(size_t)c * D_ + k4];
            Ks[(k4 + 0) * P + c] = t.x;
            Ks[(k4 + 1) * P + c] = t.y;
            Ks[(k4 + 2) * P + c] = t.z;
            Ks[(k4 + 3) * P + c] = t.w;
        }
        for (int i = tid; i < 64 * 16; i += 256) {
            int r = i >> 4, c4 = (i & 15) * 4;
            float4 t = *(const float4*)&vbase[(size_t)r * D_ + c4];
            *(float4*)&Vs[r * P + c4] = t;
        }
        __syncthreads();

        // S = Q K^T : 2 conflict-free LDS.128 per 16 FMA
        bool diag = (kt == qt);
        float sc[4][4] = {};
        #pragma unroll 8
        for (int kk = 0; kk < 64; kk++) {
            float4 a4 = *(const float4*)&Qs[kk * P + ty * 4];
            float4 b4 = *(const float4*)&Ks[kk * P + tx * 4];
            float av[4] = {a4.x, a4.y, a4.z, a4.w};
            float bv[4] = {b4.x, b4.y, b4.z, b4.w};
            #pragma unroll
            for (int i = 0; i < 4; i++)
                #pragma unroll
                for (int j = 0; j < 4; j++)
                    sc[i][j] = fmaf(av[i], bv[j], sc[i][j]);
        }
        #pragma unroll
        for (int i = 0; i < 4; i++) {
            int r = ty * 4 + i;
            if (diag) {
                #pragma unroll
                for (int j = 0; j < 4; j++)
                    if (tx * 4 + j > r) sc[i][j] = -1e30f;
            }
            float4 o = {sc[i][0], sc[i][1], sc[i][2], sc[i][3]};
            *(float4*)&Ss[r * P + tx * 4] = o;   // conflict-free f4 store
        }
        __syncthreads();

        // Online softmax: 4 threads per row, quad shuffle reduce
        {
            int r = tid >> 2, tg = tid & 3;
            float rm = -1e30f;
            #pragma unroll
            for (int jj = 0; jj < 16; jj++)
                rm = fmaxf(rm, Ss[r * P + tg + 4 * jj]);
            rm = fmaxf(rm, __shfl_xor_sync(0xffffffffu, rm, 1));
            rm = fmaxf(rm, __shfl_xor_sync(0xffffffffu, rm, 2));
            float mo = mrow[r];
            float nm = fmaxf(mo, rm);
            float sum = 0.0f;
            #pragma unroll
            for (int jj = 0; jj < 16; jj++) {
                int c = tg + 4 * jj;
                float p = __expf(Ss[r * P + c] - nm);
                Ss[r * P + c] = p;
                sum += p;
            }
            sum += __shfl_xor_sync(0xffffffffu, sum, 1);
            sum += __shfl_xor_sync(0xffffffffu, sum, 2);
            if (tg == 0) {
                float corr = __expf(mo - nm);
                lrow[r] = lrow[r] * corr + sum;
                mrow[r] = nm;
                srow[r] = corr;
            }
        }
        __syncthreads();

        // O = O*corr + P @ V  (pv = broadcast scalars, vv = LDS.128)
        #pragma unroll
        for (int i = 0; i < 4; i++) {
            float cr = srow[ty * 4 + i];
            #pragma unroll
            for (int j = 0; j < 4; j++) acc[i][j] *= cr;
        }
        #pragma unroll 8
        for (int c = 0; c < 64; c++) {
            float4 v4 = *(const float4*)&Vs[c * P + tx * 4];
            float vv[4] = {v4.x, v4.y, v4.z, v4.w};
            float pv[4];
            #pragma unroll
            for (int i = 0; i < 4; i++) pv[i] = Ss[(ty * 4 + i) * P + c];
            #pragma unroll
            for (int i = 0; i < 4; i++)
                #pragma unroll
                for (int j = 0; j < 4; j++)
                    acc[i][j] = fmaf(pv[i], vv[j], acc[i][j]);
        }
    }

    // Normalize and write [B, S, H*Dh] layout
    float* obase = att + ((size_t)(b * S_ + qt * 64)) * D_ + h * DH_;
    #pragma unroll
    for (int i = 0; i < 4; i++) {
        float inv = 1.0f / lrow[ty * 4 + i];
        float4 o = {acc[i][0] * inv, acc[i][1] * inv,
                    acc[i][2] * inv, acc[i][3] * inv};
        *(float4*)&obase[(size_t)(ty * 4 + i) * D_ + tx * 4] = o;
    }
}

// ---------------------------------------------------------------------------

extern "C" void kernel_launch(void* const* d_in, const int* in_sizes, int n_in,
                              void* d_out, int out_size)
{
    const float* x  = (const float*)d_in[0];
    const float* wq = (const float*)d_in[1];
    const float* wk = (const float*)d_in[2];
    const float* wv = (const float*)d_in[3];
    const float* wo = (const float*)d_in[4];
    float* out = (float*)d_out;

    float *q, *k, *v, *att;
    cudaGetSymbolAddress((void**)&q,   g_q);
    cudaGetSymbolAddress((void**)&k,   g_k);
    cudaGetSymbolAddress((void**)&v,   g_v);
    cudaGetSymbolAddress((void**)&att, g_att);

    dim3 gg(D_ / 128, NT_ / 128);   // (8, 32)
    gemm_nt_kernel<<<gg, 256>>>(x, wq, q, NT_, D_, D_);
    gemm_nt_kernel<<<gg, 256>>>(x, wk, k, NT_, D_, D_);
    gemm_nt_kernel<<<gg, 256>>>(x, wv, v, NT_, D_, D_);

    int smem = (4 * 64 * 68 + 3 * 64) * (int)sizeof(float);  // 70400 B
    cudaFuncSetAttribute(attn_kernel,
                         cudaFuncAttributeMaxDynamicSharedMemorySize, smem);
    dim3 ga(S_ / 64, H_, B_);       // (32, 16, 2)
    attn_kernel<<<ga, 256, smem>>>(q, k, v, att);

    gemm_nt_kernel<<<gg, 256>>>(att, wo, out, NT_, D_, D_);
}

// round 4
// speedup vs baseline: 2.3763x; 1.5936x over previous
#include <cuda_runtime.h>
#include <cuda_fp16.h>
#include <stdint.h>
#include <math.h>

#define B_   2
#define S_   2048
#define D_   1024
#define H_   16
#define DH_  64
#define NT_  (B_ * S_)          // 4096 tokens

// Scratch (allocation-free rule -> __device__ globals)
__device__ float  g_q[NT_ * D_];
__device__ float  g_k[NT_ * D_];
__device__ float  g_v[NT_ * D_];
__device__ float  g_att[NT_ * D_];
__device__ __half g_xh[NT_ * D_];
__device__ __half g_atth[NT_ * D_];
__device__ __half g_wqh[D_ * D_];
__device__ __half g_wkh[D_ * D_];
__device__ __half g_wvh[D_ * D_];
__device__ __half g_woh[D_ * D_];

// ---------------------------------------------------------------------------
// fp32 -> fp16 elementwise convert (n multiple of 4)
// ---------------------------------------------------------------------------
__global__ void f32_to_f16_kernel(const float* __restrict__ in,
                                  __half* __restrict__ out, int n)
{
    int i = (blockIdx.x * blockDim.x + threadIdx.x) * 4;
    if (i < n) {
        float4 v = *(const float4*)&in[i];
        __half2 h0 = __floats2half2_rn(v.x, v.y);
        __half2 h1 = __floats2half2_rn(v.z, v.w);
        *(__half2*)&out[i]     = h0;
        *(__half2*)&out[i + 2] = h1;
    }
}

// ---------------------------------------------------------------------------
// C[M,N] = A[M,K] @ W[N,K]^T  in fp16 via mma.sync.m16n8k16 (f32 accum).
// Block 128x128, BK=32, 8 warps (2x4), warp tile 64x32 (4x4 mma grid).
// Fragments via direct conflict-light LDS.32 (pitch 40 halves = 80B).
// ---------------------------------------------------------------------------
#define LDA 40

__global__ __launch_bounds__(256, 2) void gemm_nt_f16_kernel(
    const __half* __restrict__ A, const __half* __restrict__ W,
    float* __restrict__ C, int M, int N, int K)
{
    __shared__ __half As[128 * LDA];
    __shared__ __half Bs[128 * LDA];

    int tid  = threadIdx.x;
    int wid  = tid >> 5, lane = tid & 31;
    int gid  = lane >> 2, tig = lane & 3;
    int wm   = (wid & 1) * 64;      // warp m offset in tile
    int wn   = (wid >> 1) * 32;     // warp n offset in tile
    int m0   = blockIdx.y * 128;
    int n0   = blockIdx.x * 128;

    float acc[4][4][4] = {};        // [mtile][ntile][c0..c3]

    for (int k0 = 0; k0 < K; k0 += 32) {
        #pragma unroll
        for (int u = 0; u < 2; u++) {
            int idx = tid + u * 256;            // 0..511
            int row = idx >> 2, q = (idx & 3) * 8;
            *(int4*)&As[row * LDA + q] =
                *(const int4*)&A[(size_t)(m0 + row) * K + k0 + q];
            *(int4*)&Bs[row * LDA + q] =
                *(const int4*)&W[(size_t)(n0 + row) * K + k0 + q];
        }
        __syncthreads();

        #pragma unroll
        for (int ks = 0; ks < 2; ks++) {
            int kb = ks * 16;
            uint32_t af[4][4], bf[4][2];
            #pragma unroll
            for (int i = 0; i < 4; i++) {
                const __half* ap = &As[(wm + i * 16 + gid) * LDA + kb + tig * 2];
                af[i][0] = *(const uint32_t*)(ap);               // row,   k
                af[i][1] = *(const uint32_t*)(ap + 8 * LDA);     // row+8, k
                af[i][2] = *(const uint32_t*)(ap + 8);           // row,   k+8
                af[i][3] = *(const uint32_t*)(ap + 8 * LDA + 8); // row+8, k+8
            }
            #pragma unroll
            for (int j = 0; j < 4; j++) {
                const __half* bp = &Bs[(wn + j * 8 + gid) * LDA + kb + tig * 2];
                bf[j][0] = *(const uint32_t*)(bp);
                bf[j][1] = *(const uint32_t*)(bp + 8);
            }
            #pragma unroll
            for (int i = 0; i < 4; i++)
                #pragma unroll
                for (int j = 0; j < 4; j++)
                    asm volatile(
                        "mma.sync.aligned.m16n8k16.row.col.f32.f16.f16.f32 "
                        "{%0,%1,%2,%3}, {%4,%5,%6,%7}, {%8,%9}, {%0,%1,%2,%3};\n"
                        : "+f"(acc[i][j][0]), "+f"(acc[i][j][1]),
                          "+f"(acc[i][j][2]), "+f"(acc[i][j][3])
                        : "r"(af[i][0]), "r"(af[i][1]),
                          "r"(af[i][2]), "r"(af[i][3]),
                          "r"(bf[j][0]), "r"(bf[j][1]));
        }
        __syncthreads();
    }

    #pragma unroll
    for (int i = 0; i < 4; i++)
        #pragma unroll
        for (int j = 0; j < 4; j++) {
            int r = m0 + wm + i * 16 + gid;
            int c = n0 + wn + j * 8 + tig * 2;
            float2 lo = {acc[i][j][0], acc[i][j][1]};
            float2 hi = {acc[i][j][2], acc[i][j][3]};
            *(float2*)&C[(size_t)r * N + c]       = lo;
            *(float2*)&C[(size_t)(r + 8) * N + c] = hi;
        }
}

// ---------------------------------------------------------------------------
// Causal flash attention, fp32 (unchanged — tensorize next round).
// ---------------------------------------------------------------------------
__global__ __launch_bounds__(256) void attn_kernel(
    const float* __restrict__ q, const float* __restrict__ k,
    const float* __restrict__ v, float* __restrict__ att)
{
    const int P = 68;
    extern __shared__ float sm[];
    float* Qs   = sm;                  // [64 k][68]  transposed
    float* Ks   = Qs + 64 * P;         // [64 k][68]  transposed
    float* Vs   = Ks + 64 * P;         // [64 c][68]  row-major
    float* Ss   = Vs + 64 * P;         // [64 r][68]  row-major
    float* mrow = Ss + 64 * P;
    float* lrow = mrow + 64;
    float* srow = lrow + 64;

    int tid = threadIdx.x;
    int tx = tid & 15;
    int ty = tid >> 4;
    int qt = blockIdx.x;
    int h  = blockIdx.y;
    int b  = blockIdx.z;

    const float scale = 0.125f;

    const float* qbase = q + ((size_t)(b * S_ + qt * 64)) * D_ + h * DH_;
    for (int i = tid; i < 64 * 16; i += 256) {
        int r = i & 63, k4 = (i >> 6) * 4;
        float4 t = *(const float4*)&qbase[(size_t)r * D_ + k4];
        Qs[(k4 + 0) * P + r] = t.x * scale;
        Qs[(k4 + 1) * P + r] = t.y * scale;
        Qs[(k4 + 2) * P + r] = t.z * scale;
        Qs[(k4 + 3) * P + r] = t.w * scale;
    }
    if (tid < 64) { mrow[tid] = -1e30f; lrow[tid] = 0.0f; }

    float acc[4][4] = {};

    for (int kt = 0; kt <= qt; kt++) {
        __syncthreads();
        const float* kbase = k + ((size_t)(b * S_ + kt * 64)) * D_ + h * DH_;
        const float* vbase = v + ((size_t)(b * S_ + kt * 64)) * D_ + h * DH_;
        for (int i = tid; i < 64 * 16; i += 256) {
            int c = i & 63, k4 = (i >> 6) * 4;
            float4 t = *(const float4*)&kbase[(size_t)c * D_ + k4];
            Ks[(k4 + 0) * P + c] = t.x;
            Ks[(k4 + 1) * P + c] = t.y;
            Ks[(k4 + 2) * P + c] = t.z;
            Ks[(k4 + 3) * P + c] = t.w;
        }
        for (int i = tid; i < 64 * 16; i += 256) {
            int r = i >> 4, c4 = (i & 15) * 4;
            float4 t = *(const float4*)&vbase[(size_t)r * D_ + c4];
            *(float4*)&Vs[r * P + c4] = t;
        }
        __syncthreads();

        bool diag = (kt == qt);
        float sc[4][4] = {};
        #pragma unroll 8
        for (int kk = 0; kk < 64; kk++) {
            float4 a4 = *(const float4*)&Qs[kk * P + ty * 4];
            float4 b4 = *(const float4*)&Ks[kk * P + tx * 4];
            float av[4] = {a4.x, a4.y, a4.z, a4.w};
            float bv[4] = {b4.x, b4.y, b4.z, b4.w};
            #pragma unroll
            for (int i = 0; i < 4; i++)
                #pragma unroll
                for (int j = 0; j < 4; j++)
                    sc[i][j] = fmaf(av[i], bv[j], sc[i][j]);
        }
        #pragma unroll
        for (int i = 0; i < 4; i++) {
            int r = ty * 4 + i;
            if (diag) {
                #pragma unroll
                for (int j = 0; j < 4; j++)
                    if (tx * 4 + j > r) sc[i][j] = -1e30f;
            }
            float4 o = {sc[i][0], sc[i][1], sc[i][2], sc[i][3]};
            *(float4*)&Ss[r * P + tx * 4] = o;
        }
        __syncthreads();

        {
            int r = tid >> 2, tg = tid & 3;
            float rm = -1e30f;
            #pragma unroll
            for (int jj = 0; jj < 16; jj++)
                rm = fmaxf(rm, Ss[r * P + tg + 4 * jj]);
            rm = fmaxf(rm, __shfl_xor_sync(0xffffffffu, rm, 1));
            rm = fmaxf(rm, __shfl_xor_sync(0xffffffffu, rm, 2));
            float mo = mrow[r];
            float nm = fmaxf(mo, rm);
            float sum = 0.0f;
            #pragma unroll
            for (int jj = 0; jj < 16; jj++) {
                int c = tg + 4 * jj;
                float p = __expf(Ss[r * P + c] - nm);
                Ss[r * P + c] = p;
                sum += p;
            }
            sum += __shfl_xor_sync(0xffffffffu, sum, 1);
            sum += __shfl_xor_sync(0xffffffffu, sum, 2);
            if (tg == 0) {
                float corr = __expf(mo - nm);
                lrow[r] = lrow[r] * corr + sum;
                mrow[r] = nm;
                srow[r] = corr;
            }
        }
        __syncthreads();

        #pragma unroll
        for (int i = 0; i < 4; i++) {
            float cr = srow[ty * 4 + i];
            #pragma unroll
            for (int j = 0; j < 4; j++) acc[i][j] *= cr;
        }
        #pragma unroll 8
        for (int c = 0; c < 64; c++) {
            float4 v4 = *(const float4*)&Vs[c * P + tx * 4];
            float vv[4] = {v4.x, v4.y, v4.z, v4.w};
            float pv[4];
            #pragma unroll
            for (int i = 0; i < 4; i++) pv[i] = Ss[(ty * 4 + i) * P + c];
            #pragma unroll
            for (int i = 0; i < 4; i++)
                #pragma unroll
                for (int j = 0; j < 4; j++)
                    acc[i][j] = fmaf(pv[i], vv[j], acc[i][j]);
        }
    }

    float* obase = att + ((size_t)(b * S_ + qt * 64)) * D_ + h * DH_;
    #pragma unroll
    for (int i = 0; i < 4; i++) {
        float inv = 1.0f / lrow[ty * 4 + i];
        float4 o = {acc[i][0] * inv, acc[i][1] * inv,
                    acc[i][2] * inv, acc[i][3] * inv};
        *(float4*)&obase[(size_t)(ty * 4 + i) * D_ + tx * 4] = o;
    }
}

// ---------------------------------------------------------------------------

extern "C" void kernel_launch(void* const* d_in, const int* in_sizes, int n_in,
                              void* d_out, int out_size)
{
    const float* x  = (const float*)d_in[0];
    const float* wq = (const float*)d_in[1];
    const float* wk = (const float*)d_in[2];
    const float* wv = (const float*)d_in[3];
    const float* wo = (const float*)d_in[4];
    float* out = (float*)d_out;

    float *q, *k, *v, *att;
    __half *xh, *atth, *wqh, *wkh, *wvh, *woh;
    cudaGetSymbolAddress((void**)&q,    g_q);
    cudaGetSymbolAddress((void**)&k,    g_k);
    cudaGetSymbolAddress((void**)&v,    g_v);
    cudaGetSymbolAddress((void**)&att,  g_att);
    cudaGetSymbolAddress((void**)&xh,   g_xh);
    cudaGetSymbolAddress((void**)&atth, g_atth);
    cudaGetSymbolAddress((void**)&wqh,  g_wqh);
    cudaGetSymbolAddress((void**)&wkh,  g_wkh);
    cudaGetSymbolAddress((void**)&wvh,  g_wvh);
    cudaGetSymbolAddress((void**)&woh,  g_woh);

    const int NX = NT_ * D_;          // 4M
    const int NW = D_ * D_;           // 1M
    f32_to_f16_kernel<<<NX / 1024, 256>>>(x,  xh,  NX);
    f32_to_f16_kernel<<<NW / 1024, 256>>>(wq, wqh, NW);
    f32_to_f16_kernel<<<NW / 1024, 256>>>(wk, wkh, NW);
    f32_to_f16_kernel<<<NW / 1024, 256>>>(wv, wvh, NW);
    f32_to_f16_kernel<<<NW / 1024, 256>>>(wo, woh, NW);

    dim3 gg(D_ / 128, NT_ / 128);     // (8, 32)
    gemm_nt_f16_kernel<<<gg, 256>>>(xh, wqh, q, NT_, D_, D_);
    gemm_nt_f16_kernel<<<gg, 256>>>(xh, wkh, k, NT_, D_, D_);
    gemm_nt_f16_kernel<<<gg, 256>>>(xh, wvh, v, NT_, D_, D_);

    int smem = (4 * 64 * 68 + 3 * 64) * (int)sizeof(float);  // 70400 B
    cudaFuncSetAttribute(attn_kernel,
                         cudaFuncAttributeMaxDynamicSharedMemorySize, smem);
    dim3 ga(S_ / 64, H_, B_);         // (32, 16, 2)
    attn_kernel<<<ga, 256, smem>>>(q, k, v, att);

    f32_to_f16_kernel<<<NX / 1024, 256>>>(att, atth, NX);
    gemm_nt_f16_kernel<<<gg, 256>>>(atth, woh, out, NT_, D_, D_);
}

// round 6
// speedup vs baseline: 6.7463x; 2.8390x over previous
#include <cuda_runtime.h>
#include <cuda_fp16.h>
#include <stdint.h>
#include <math.h>

#define B_   2
#define S_   2048
#define D_   1024
#define H_   16
#define DH_  64
#define NT_  (B_ * S_)          // 4096 tokens

// Scratch (allocation-free rule -> __device__ globals)
__device__ __half g_qh[NT_ * D_];
__device__ __half g_kh[NT_ * D_];
__device__ __half g_vh[NT_ * D_];
__device__ __half g_atth[NT_ * D_];
__device__ __half g_xh[NT_ * D_];
__device__ __half g_wqh[D_ * D_];
__device__ __half g_wkh[D_ * D_];
__device__ __half g_wvh[D_ * D_];
__device__ __half g_woh[D_ * D_];

__device__ __forceinline__ void mma16816(float* c, const uint32_t* a,
                                         uint32_t b0, uint32_t b1)
{
    asm volatile(
        "mma.sync.aligned.m16n8k16.row.col.f32.f16.f16.f32 "
        "{%0,%1,%2,%3}, {%4,%5,%6,%7}, {%8,%9}, {%0,%1,%2,%3};\n"
        : "+f"(c[0]), "+f"(c[1]), "+f"(c[2]), "+f"(c[3])
        : "r"(a[0]), "r"(a[1]), "r"(a[2]), "r"(a[3]), "r"(b0), "r"(b1));
}

// ---------------------------------------------------------------------------
// fp32 -> fp16 elementwise convert (n multiple of 4)
// ---------------------------------------------------------------------------
__global__ void f32_to_f16_kernel(const float* __restrict__ in,
                                  __half* __restrict__ out, int n)
{
    int i = (blockIdx.x * blockDim.x + threadIdx.x) * 4;
    if (i < n) {
        float4 v = *(const float4*)&in[i];
        *(__half2*)&out[i]     = __floats2half2_rn(v.x, v.y);
        *(__half2*)&out[i + 2] = __floats2half2_rn(v.z, v.w);
    }
}

// ---------------------------------------------------------------------------
// C[M,N] = A[M,K] @ W[N,K]^T  fp16 mma, f32 accum, OutT epilogue.
// Block 128x128, BK=32, 8 warps, warp tile 64x32.
// ---------------------------------------------------------------------------
#define LDA 40

template <typename OutT>
__global__ __launch_bounds__(256, 2) void gemm_nt_f16_kernel(
    const __half* __restrict__ A, const __half* __restrict__ W,
    OutT* __restrict__ C, int M, int N, int K)
{
    __shared__ __half As[128 * LDA];
    __shared__ __half Bs[128 * LDA];

    int tid  = threadIdx.x;
    int wid  = tid >> 5, lane = tid & 31;
    int gid  = lane >> 2, tig = lane & 3;
    int wm   = (wid & 1) * 64;
    int wn   = (wid >> 1) * 32;
    int m0   = blockIdx.y * 128;
    int n0   = blockIdx.x * 128;

    float acc[4][4][4] = {};

    for (int k0 = 0; k0 < K; k0 += 32) {
        #pragma unroll
        for (int u = 0; u < 2; u++) {
            int idx = tid + u * 256;
            int row = idx >> 2, q = (idx & 3) * 8;
            *(int4*)&As[row * LDA + q] =
                *(const int4*)&A[(size_t)(m0 + row) * K + k0 + q];
            *(int4*)&Bs[row * LDA + q] =
                *(const int4*)&W[(size_t)(n0 + row) * K + k0 + q];
        }
        __syncthreads();

        #pragma unroll
        for (int ks = 0; ks < 2; ks++) {
            int kb = ks * 16;
            uint32_t af[4][4], bf[4][2];
            #pragma unroll
            for (int i = 0; i < 4; i++) {
                const __half* ap = &As[(wm + i * 16 + gid) * LDA + kb + tig * 2];
                af[i][0] = *(const uint32_t*)(ap);
                af[i][1] = *(const uint32_t*)(ap + 8 * LDA);
                af[i][2] = *(const uint32_t*)(ap + 8);
                af[i][3] = *(const uint32_t*)(ap + 8 * LDA + 8);
            }
            #pragma unroll
            for (int j = 0; j < 4; j++) {
                const __half* bp = &Bs[(wn + j * 8 + gid) * LDA + kb + tig * 2];
                bf[j][0] = *(const uint32_t*)(bp);
                bf[j][1] = *(const uint32_t*)(bp + 8);
            }
            #pragma unroll
            for (int i = 0; i < 4; i++)
                #pragma unroll
                for (int j = 0; j < 4; j++)
                    mma16816(acc[i][j], af[i], bf[j][0], bf[j][1]);
        }
        __syncthreads();
    }

    #pragma unroll
    for (int i = 0; i < 4; i++)
        #pragma unroll
        for (int j = 0; j < 4; j++) {
            int r = m0 + wm + i * 16 + gid;
            int c = n0 + wn + j * 8 + tig * 2;
            if (sizeof(OutT) == 2) {
                *(__half2*)((__half*)C + (size_t)r * N + c) =
                    __floats2half2_rn(acc[i][j][0], acc[i][j][1]);
                *(__half2*)((__half*)C + (size_t)(r + 8) * N + c) =
                    __floats2half2_rn(acc[i][j][2], acc[i][j][3]);
            } else {
                float2 lo = {acc[i][j][0], acc[i][j][1]};
                float2 hi = {acc[i][j][2], acc[i][j][3]};
                *(float2*)((float*)C + (size_t)r * N + c)       = lo;
                *(float2*)((float*)C + (size_t)(r + 8) * N + c) = hi;
            }
        }
}

// ---------------------------------------------------------------------------
// Causal flash attention, fp16 tensor cores (FA2 register-resident).
// Block: 128 q-rows, 8 warps (one m16 each), KV tile 64 keys, Dh=64.
// ---------------------------------------------------------------------------
#define LKV 72   // smem pitch in halves for K/V tiles

__global__ __launch_bounds__(256, 2) void attn_f16_kernel(
    const __half* __restrict__ qh, const __half* __restrict__ kh,
    const __half* __restrict__ vh, __half* __restrict__ oh)
{
    __shared__ __half Ks[64 * LKV];
    __shared__ __half Vs[64 * LKV];

    int tid = threadIdx.x, wid = tid >> 5, lane = tid & 31;
    int gid = lane >> 2, tig = lane & 3;
    int q0 = blockIdx.x * 128;
    int h  = blockIdx.y, b = blockIdx.z;
    size_t base = ((size_t)b * S_) * D_ + h * DH_;
    int wrow = wid * 16;
    int row0 = q0 + wrow + gid;     // global seq row for c0/c1 lanes

    const __half* qb = qh + base;
    const __half* kb = kh + base;
    const __half* vb = vh + base;

    // Q fragments: [k-chunk][a0..a3], loaded once
    uint32_t qf[4][4];
    #pragma unroll
    for (int kc = 0; kc < 4; kc++) {
        const __half* p0 = &qb[(size_t)row0 * D_ + kc * 16 + tig * 2];
        const __half* p1 = &qb[(size_t)(row0 + 8) * D_ + kc * 16 + tig * 2];
        qf[kc][0] = *(const uint32_t*)(p0);
        qf[kc][1] = *(const uint32_t*)(p1);
        qf[kc][2] = *(const uint32_t*)(p0 + 8);
        qf[kc][3] = *(const uint32_t*)(p1 + 8);
    }

    float m0r = -1e30f, m1r = -1e30f, l0r = 0.0f, l1r = 0.0f;
    float oacc[8][4] = {};
    const float scale = 0.125f;

    int ntiles = (q0 >> 6) + 2;
    for (int kt = 0; kt < ntiles; kt++) {
        int kv0 = kt * 64;
        __syncthreads();
        #pragma unroll
        for (int u = 0; u < 2; u++) {
            int idx = tid + u * 256;            // 0..511
            int row = idx >> 3, off = (idx & 7) * 8;
            *(int4*)&Ks[row * LKV + off] =
                *(const int4*)&kb[(size_t)(kv0 + row) * D_ + off];
            *(int4*)&Vs[row * LKV + off] =
                *(const int4*)&vb[(size_t)(kv0 + row) * D_ + off];
        }
        __syncthreads();

        // S = Q K^T : acc tile j covers keys kv0 + j*8 + {tig*2, tig*2+1}
        float sacc[8][4] = {};
        #pragma unroll
        for (int kc = 0; kc < 4; kc++)
            #pragma unroll
            for (int j = 0; j < 8; j++) {
                const __half* bp = &Ks[(j * 8 + gid) * LKV + kc * 16 + tig * 2];
                mma16816(sacc[j], qf[kc],
                         *(const uint32_t*)(bp), *(const uint32_t*)(bp + 8));
            }

        // scale + causal mask
        bool need_mask = (kv0 + 63 > q0 + wrow);
        #pragma unroll
        for (int j = 0; j < 8; j++) {
            int c0 = kv0 + j * 8 + tig * 2;
            #pragma unroll
            for (int u = 0; u < 4; u++) sacc[j][u] *= scale;
            if (need_mask) {
                if (c0     > row0)     sacc[j][0] = -1e30f;
                if (c0 + 1 > row0)     sacc[j][1] = -1e30f;
                if (c0     > row0 + 8) sacc[j][2] = -1e30f;
                if (c0 + 1 > row0 + 8) sacc[j][3] = -1e30f;
            }
        }

        // online softmax (rows gid, gid+8; quad = row group)
        float rm0 = -1e30f, rm1 = -1e30f;
        #pragma unroll
        for (int j = 0; j < 8; j++) {
            rm0 = fmaxf(rm0, fmaxf(sacc[j][0], sacc[j][1]));
            rm1 = fmaxf(rm1, fmaxf(sacc[j][2], sacc[j][3]));
        }
        rm0 = fmaxf(rm0, __shfl_xor_sync(0xffffffffu, rm0, 1));
        rm0 = fmaxf(rm0, __shfl_xor_sync(0xffffffffu, rm0, 2));
        rm1 = fmaxf(rm1, __shfl_xor_sync(0xffffffffu, rm1, 1));
        rm1 = fmaxf(rm1, __shfl_xor_sync(0xffffffffu, rm1, 2));
        float nm0 = fmaxf(m0r, rm0), nm1 = fmaxf(m1r, rm1);
        float corr0 = __expf(m0r - nm0), corr1 = __expf(m1r - nm1);
        m0r = nm0; m1r = nm1;

        float sum0 = 0.0f, sum1 = 0.0f;
        #pragma unroll
        for (int j = 0; j < 8; j++) {
            sacc[j][0] = __expf(sacc[j][0] - nm0);
            sacc[j][1] = __expf(sacc[j][1] - nm0);
            sacc[j][2] = __expf(sacc[j][2] - nm1);
            sacc[j][3] = __expf(sacc[j][3] - nm1);
            sum0 += sacc[j][0] + sacc[j][1];
            sum1 += sacc[j][2] + sacc[j][3];
        }
        sum0 += __shfl_xor_sync(0xffffffffu, sum0, 1);
        sum0 += __shfl_xor_sync(0xffffffffu, sum0, 2);
        sum1 += __shfl_xor_sync(0xffffffffu, sum1, 1);
        sum1 += __shfl_xor_sync(0xffffffffu, sum1, 2);
        l0r = l0r * corr0 + sum0;
        l1r = l1r * corr1 + sum1;

        // rescale O
        #pragma unroll
        for (int j = 0; j < 8; j++) {
            oacc[j][0] *= corr0; oacc[j][1] *= corr0;
            oacc[j][2] *= corr1; oacc[j][3] *= corr1;
        }

        // O += P @ V  (P fragments repacked from sacc; V via ldmatrix.trans)
        int mi = lane >> 3, rr = lane & 7;
        #pragma unroll
        for (int kc = 0; kc < 4; kc++) {
            uint32_t pf[4];
            __half2 h0 = __floats2half2_rn(sacc[2*kc][0],   sacc[2*kc][1]);
            __half2 h1 = __floats2half2_rn(sacc[2*kc][2],   sacc[2*kc][3]);
            __half2 h2 = __floats2half2_rn(sacc[2*kc+1][0], sacc[2*kc+1][1]);
            __half2 h3 = __floats2half2_rn(sacc[2*kc+1][2], sacc[2*kc+1][3]);
            pf[0] = *(uint32_t*)&h0; pf[1] = *(uint32_t*)&h1;
            pf[2] = *(uint32_t*)&h2; pf[3] = *(uint32_t*)&h3;

            #pragma unroll
            for (int jop = 0; jop < 4; jop++) {
                uint32_t r0, r1, r2, r3;
                const __half* vp = &Vs[(kc * 16 + (mi & 1) * 8 + rr) * LKV
                                       + jop * 16 + (mi >> 1) * 8];
                uint32_t va = (uint32_t)__cvta_generic_to_shared(vp);
                asm volatile(
                    "ldmatrix.sync.aligned.m8n8.x4.trans.shared.b16 "
                    "{%0,%1,%2,%3}, [%4];"
                    : "=r"(r0), "=r"(r1), "=r"(r2), "=r"(r3) : "r"(va));
                mma16816(oacc[2 * jop],     pf, r0, r1);
                mma16816(oacc[2 * jop + 1], pf, r2, r3);
            }
        }
    }

    // normalize + store fp16
    float inv0 = 1.0f / l0r, inv1 = 1.0f / l1r;
    __half* ob = oh + base;
    #pragma unroll
    for (int j = 0; j < 8; j++) {
        int c = j * 8 + tig * 2;
        *(__half2*)&ob[(size_t)row0 * D_ + c] =
            __floats2half2_rn(oacc[j][0] * inv0, oacc[j][1] * inv0);
        *(__half2*)&ob[(size_t)(row0 + 8) * D_ + c] =
            __floats2half2_rn(oacc[j][2] * inv1, oacc[j][3] * inv1);
    }
}

// ---------------------------------------------------------------------------

extern "C" void kernel_launch(void* const* d_in, const int* in_sizes, int n_in,
                              void* d_out, int out_size)
{
    const float* x  = (const float*)d_in[0];
    const float* wq = (const float*)d_in[1];
    const float* wk = (const float*)d_in[2];
    const float* wv = (const float*)d_in[3];
    const float* wo = (const float*)d_in[4];
    float* out = (float*)d_out;

    __half *qh, *kh, *vh, *atth, *xh, *wqh, *wkh, *wvh, *woh;
    cudaGetSymbolAddress((void**)&qh,   g_qh);
    cudaGetSymbolAddress((void**)&kh,   g_kh);
    cudaGetSymbolAddress((void**)&vh,   g_vh);
    cudaGetSymbolAddress((void**)&atth, g_atth);
    cudaGetSymbolAddress((void**)&xh,   g_xh);
    cudaGetSymbolAddress((void**)&wqh,  g_wqh);
    cudaGetSymbolAddress((void**)&wkh,  g_wkh);
    cudaGetSymbolAddress((void**)&wvh,  g_wvh);
    cudaGetSymbolAddress((void**)&woh,  g_woh);

    const int NX = NT_ * D_;          // 4M
    const int NW = D_ * D_;           // 1M
    f32_to_f16_kernel<<<NX / 1024, 256>>>(x,  xh,  NX);
    f32_to_f16_kernel<<<NW / 1024, 256>>>(wq, wqh, NW);
    f32_to_f16_kernel<<<NW / 1024, 256>>>(wk, wkh, NW);
    f32_to_f16_kernel<<<NW / 1024, 256>>>(wv, wvh, NW);
    f32_to_f16_kernel<<<NW / 1024, 256>>>(wo, woh, NW);

    dim3 gg(D_ / 128, NT_ / 128);     // (8, 32)
    gemm_nt_f16_kernel<__half><<<gg, 256>>>(xh, wqh, qh, NT_, D_, D_);
    gemm_nt_f16_kernel<__half><<<gg, 256>>>(xh, wkh, kh, NT_, D_, D_);
    gemm_nt_f16_kernel<__half><<<gg, 256>>>(xh, wvh, vh, NT_, D_, D_);

    dim3 ga(S_ / 128, H_, B_);        // (16, 16, 2)
    attn_f16_kernel<<<ga, 256>>>(qh, kh, vh, atth);

    gemm_nt_f16_kernel<float><<<gg, 256>>>(atth, woh, out, NT_, D_, D_);
}

// round 7
// speedup vs baseline: 7.8513x; 1.1638x over previous
#include <cuda_runtime.h>
#include <cuda_fp16.h>
#include <stdint.h>
#include <math.h>

#define B_   2
#define S_   2048
#define D_   1024
#define H_   16
#define DH_  64
#define NT_  (B_ * S_)          // 4096 tokens

// Scratch (allocation-free rule -> __device__ globals)
__device__ __half g_qh[NT_ * D_];
__device__ __half g_kh[NT_ * D_];
__device__ __half g_vh[NT_ * D_];
__device__ __half g_atth[NT_ * D_];
__device__ __half g_xh[NT_ * D_];
__device__ __half g_wqh[D_ * D_];
__device__ __half g_wkh[D_ * D_];
__device__ __half g_wvh[D_ * D_];
__device__ __half g_woh[D_ * D_];

__device__ __forceinline__ void mma16816(float* c, const uint32_t* a,
                                         uint32_t b0, uint32_t b1)
{
    asm volatile(
        "mma.sync.aligned.m16n8k16.row.col.f32.f16.f16.f32 "
        "{%0,%1,%2,%3}, {%4,%5,%6,%7}, {%8,%9}, {%0,%1,%2,%3};\n"
        : "+f"(c[0]), "+f"(c[1]), "+f"(c[2]), "+f"(c[3])
        : "r"(a[0]), "r"(a[1]), "r"(a[2]), "r"(a[3]), "r"(b0), "r"(b1));
}

__device__ __forceinline__ void cp16(void* smem, const void* gmem)
{
    uint32_t sa = (uint32_t)__cvta_generic_to_shared(smem);
    asm volatile("cp.async.cg.shared.global [%0], [%1], 16;\n"
                 :: "r"(sa), "l"(gmem));
}
__device__ __forceinline__ void cp_commit()
{
    asm volatile("cp.async.commit_group;\n");
}

// ---------------------------------------------------------------------------
// fp32 -> fp16 elementwise convert (n multiple of 4)
// ---------------------------------------------------------------------------
__global__ void f32_to_f16_kernel(const float* __restrict__ in,
                                  __half* __restrict__ out, int n)
{
    int i = (blockIdx.x * blockDim.x + threadIdx.x) * 4;
    if (i < n) {
        float4 v = *(const float4*)&in[i];
        *(__half2*)&out[i]     = __floats2half2_rn(v.x, v.y);
        *(__half2*)&out[i + 2] = __floats2half2_rn(v.z, v.w);
    }
}

// ---------------------------------------------------------------------------
// C[M,N] = A[M,K] @ W[N,K]^T  fp16 mma, f32 accum, OutT epilogue.
// Block 128x128, BK=32, 8 warps, warp tile 64x32.
// 2-stage cp.async double buffer. NSEL>1: blockIdx.z picks W/C pair (QKV fuse).
// ---------------------------------------------------------------------------
#define LDA 40

template <typename OutT>
__global__ __launch_bounds__(256, 2) void gemm_nt_f16_kernel(
    const __half* __restrict__ A,
    const __half* __restrict__ W0, const __half* __restrict__ W1,
    const __half* __restrict__ W2,
    OutT* __restrict__ C0, OutT* __restrict__ C1, OutT* __restrict__ C2,
    int M, int N, int K)
{
    __shared__ __half As[2][128 * LDA];
    __shared__ __half Bs[2][128 * LDA];

    const __half* W = (blockIdx.z == 0) ? W0 : (blockIdx.z == 1) ? W1 : W2;
    OutT*         C = (blockIdx.z == 0) ? C0 : (blockIdx.z == 1) ? C1 : C2;

    int tid  = threadIdx.x;
    int wid  = tid >> 5, lane = tid & 31;
    int gid  = lane >> 2, tig = lane & 3;
    int wm   = (wid & 1) * 64;
    int wn   = (wid >> 1) * 32;
    int m0   = blockIdx.y * 128;
    int n0   = blockIdx.x * 128;

    int lrow = tid >> 2, lq = (tid & 3) * 8;   // A/B loader mapping (u stride 64)

    float acc[4][4][4] = {};

    const int NIT = K / 32;
    // prologue: stage 0
    #pragma unroll
    for (int u = 0; u < 2; u++) {
        int row = lrow + u * 64;
        cp16(&As[0][row * LDA + lq], &A[(size_t)(m0 + row) * K + lq]);
        cp16(&Bs[0][row * LDA + lq], &W[(size_t)(n0 + row) * K + lq]);
    }
    cp_commit();

    for (int t = 0; t < NIT; t++) {
        int b = t & 1;
        if (t + 1 < NIT) {
            int k0 = (t + 1) * 32;
            #pragma unroll
            for (int u = 0; u < 2; u++) {
                int row = lrow + u * 64;
                cp16(&As[b ^ 1][row * LDA + lq],
                     &A[(size_t)(m0 + row) * K + k0 + lq]);
                cp16(&Bs[b ^ 1][row * LDA + lq],
                     &W[(size_t)(n0 + row) * K + k0 + lq]);
            }
            cp_commit();
            asm volatile("cp.async.wait_group 1;\n");
        } else {
            asm volatile("cp.async.wait_group 0;\n");
        }
        __syncthreads();

        #pragma unroll
        for (int ks = 0; ks < 2; ks++) {
            int kb = ks * 16;
            uint32_t af[4][4], bf[4][2];
            #pragma unroll
            for (int i = 0; i < 4; i++) {
                const __half* ap = &As[b][(wm + i * 16 + gid) * LDA + kb + tig * 2];
                af[i][0] = *(const uint32_t*)(ap);
                af[i][1] = *(const uint32_t*)(ap + 8 * LDA);
                af[i][2] = *(const uint32_t*)(ap + 8);
                af[i][3] = *(const uint32_t*)(ap + 8 * LDA + 8);
            }
            #pragma unroll
            for (int j = 0; j < 4; j++) {
                const __half* bp = &Bs[b][(wn + j * 8 + gid) * LDA + kb + tig * 2];
                bf[j][0] = *(const uint32_t*)(bp);
                bf[j][1] = *(const uint32_t*)(bp + 8);
            }
            #pragma unroll
            for (int i = 0; i < 4; i++)
                #pragma unroll
                for (int j = 0; j < 4; j++)
                    mma16816(acc[i][j], af[i], bf[j][0], bf[j][1]);
        }
        __syncthreads();
    }

    #pragma unroll
    for (int i = 0; i < 4; i++)
        #pragma unroll
        for (int j = 0; j < 4; j++) {
            int r = m0 + wm + i * 16 + gid;
            int c = n0 + wn + j * 8 + tig * 2;
            if (sizeof(OutT) == 2) {
                *(__half2*)((__half*)C + (size_t)r * N + c) =
                    __floats2half2_rn(acc[i][j][0], acc[i][j][1]);
                *(__half2*)((__half*)C + (size_t)(r + 8) * N + c) =
                    __floats2half2_rn(acc[i][j][2], acc[i][j][3]);
            } else {
                float2 lo = {acc[i][j][0], acc[i][j][1]};
                float2 hi = {acc[i][j][2], acc[i][j][3]};
                *(float2*)((float*)C + (size_t)r * N + c)       = lo;
                *(float2*)((float*)C + (size_t)(r + 8) * N + c) = hi;
            }
        }
}

// ---------------------------------------------------------------------------
// Causal flash attention, fp16 tensor cores (FA2 register-resident),
// 2-stage cp.async KV pipeline.
// Block: 128 q-rows, 8 warps (one m16 each), KV tile 64 keys, Dh=64.
// ---------------------------------------------------------------------------
#define LKV 72   // smem pitch in halves for K/V tiles

__global__ __launch_bounds__(256, 2) void attn_f16_kernel(
    const __half* __restrict__ qh, const __half* __restrict__ kh,
    const __half* __restrict__ vh, __half* __restrict__ oh)
{
    __shared__ __half Ks[2][64 * LKV];
    __shared__ __half Vs[2][64 * LKV];

    int tid = threadIdx.x, wid = tid >> 5, lane = tid & 31;
    int gid = lane >> 2, tig = lane & 3;
    int q0 = blockIdx.x * 128;
    int h  = blockIdx.y, b = blockIdx.z;
    size_t base = ((size_t)b * S_) * D_ + h * DH_;
    int wrow = wid * 16;
    int row0 = q0 + wrow + gid;

    const __half* qb = qh + base;
    const __half* kb = kh + base;
    const __half* vb = vh + base;

    int lrow = tid >> 3, loff = (tid & 7) * 8;   // KV loader (u stride 32)

    // Q fragments: [k-chunk][a0..a3], loaded once
    uint32_t qf[4][4];
    #pragma unroll
    for (int kc = 0; kc < 4; kc++) {
        const __half* p0 = &qb[(size_t)row0 * D_ + kc * 16 + tig * 2];
        const __half* p1 = &qb[(size_t)(row0 + 8) * D_ + kc * 16 + tig * 2];
        qf[kc][0] = *(const uint32_t*)(p0);
        qf[kc][1] = *(const uint32_t*)(p1);
        qf[kc][2] = *(const uint32_t*)(p0 + 8);
        qf[kc][3] = *(const uint32_t*)(p1 + 8);
    }

    float m0r = -1e30f, m1r = -1e30f, l0r = 0.0f, l1r = 0.0f;
    float oacc[8][4] = {};
    const float scale = 0.125f;

    int ntiles = (q0 >> 6) + 2;

    // prologue: stage 0
    #pragma unroll
    for (int u = 0; u < 2; u++) {
        int row = lrow + u * 32;
        cp16(&Ks[0][row * LKV + loff], &kb[(size_t)row * D_ + loff]);
        cp16(&Vs[0][row * LKV + loff], &vb[(size_t)row * D_ + loff]);
    }
    cp_commit();

    for (int kt = 0; kt < ntiles; kt++) {
        int kv0 = kt * 64;
        int bs = kt & 1;
        if (kt + 1 < ntiles) {
            int nv0 = kv0 + 64;
            #pragma unroll
            for (int u = 0; u < 2; u++) {
                int row = lrow + u * 32;
                cp16(&Ks[bs ^ 1][row * LKV + loff],
                     &kb[(size_t)(nv0 + row) * D_ + loff]);
                cp16(&Vs[bs ^ 1][row * LKV + loff],
                     &vb[(size_t)(nv0 + row) * D_ + loff]);
            }
            cp_commit();
            asm volatile("cp.async.wait_group 1;\n");
        } else {
            asm volatile("cp.async.wait_group 0;\n");
        }
        __syncthreads();

        // S = Q K^T
        float sacc[8][4] = {};
        #pragma unroll
        for (int kc = 0; kc < 4; kc++)
            #pragma unroll
            for (int j = 0; j < 8; j++) {
                const __half* bp = &Ks[bs][(j * 8 + gid) * LKV + kc * 16 + tig * 2];
                mma16816(sacc[j], qf[kc],
                         *(const uint32_t*)(bp), *(const uint32_t*)(bp + 8));
            }

        // scale + causal mask
        bool need_mask = (kv0 + 63 > q0 + wrow);
        #pragma unroll
        for (int j = 0; j < 8; j++) {
            int c0 = kv0 + j * 8 + tig * 2;
            #pragma unroll
            for (int u = 0; u < 4; u++) sacc[j][u] *= scale;
            if (need_mask) {
                if (c0     > row0)     sacc[j][0] = -1e30f;
                if (c0 + 1 > row0)     sacc[j][1] = -1e30f;
                if (c0     > row0 + 8) sacc[j][2] = -1e30f;
                if (c0 + 1 > row0 + 8) sacc[j][3] = -1e30f;
            }
        }

        // online softmax (rows gid, gid+8; quad = row group)
        float rm0 = -1e30f, rm1 = -1e30f;
        #pragma unroll
        for (int j = 0; j < 8; j++) {
            rm0 = fmaxf(rm0, fmaxf(sacc[j][0], sacc[j][1]));
            rm1 = fmaxf(rm1, fmaxf(sacc[j][2], sacc[j][3]));
        }
        rm0 = fmaxf(rm0, __shfl_xor_sync(0xffffffffu, rm0, 1));
        rm0 = fmaxf(rm0, __shfl_xor_sync(0xffffffffu, rm0, 2));
        rm1 = fmaxf(rm1, __shfl_xor_sync(0xffffffffu, rm1, 1));
        rm1 = fmaxf(rm1, __shfl_xor_sync(0xffffffffu, rm1, 2));
        float nm0 = fmaxf(m0r, rm0), nm1 = fmaxf(m1r, rm1);
        float corr0 = __expf(m0r - nm0), corr1 = __expf(m1r - nm1);
        m0r = nm0; m1r = nm1;

        float sum0 = 0.0f, sum1 = 0.0f;
        #pragma unroll
        for (int j = 0; j < 8; j++) {
            sacc[j][0] = __expf(sacc[j][0] - nm0);
            sacc[j][1] = __expf(sacc[j][1] - nm0);
            sacc[j][2] = __expf(sacc[j][2] - nm1);
            sacc[j][3] = __expf(sacc[j][3] - nm1);
            sum0 += sacc[j][0] + sacc[j][1];
            sum1 += sacc[j][2] + sacc[j][3];
        }
        sum0 += __shfl_xor_sync(0xffffffffu, sum0, 1);
        sum0 += __shfl_xor_sync(0xffffffffu, sum0, 2);
        sum1 += __shfl_xor_sync(0xffffffffu, sum1, 1);
        sum1 += __shfl_xor_sync(0xffffffffu, sum1, 2);
        l0r = l0r * corr0 + sum0;
        l1r = l1r * corr1 + sum1;

        #pragma unroll
        for (int j = 0; j < 8; j++) {
            oacc[j][0] *= corr0; oacc[j][1] *= corr0;
            oacc[j][2] *= corr1; oacc[j][3] *= corr1;
        }

        // O += P @ V
        int mi = lane >> 3, rr = lane & 7;
        #pragma unroll
        for (int kc = 0; kc < 4; kc++) {
            uint32_t pf[4];
            __half2 h0 = __floats2half2_rn(sacc[2*kc][0],   sacc[2*kc][1]);
            __half2 h1 = __floats2half2_rn(sacc[2*kc][2],   sacc[2*kc][3]);
            __half2 h2 = __floats2half2_rn(sacc[2*kc+1][0], sacc[2*kc+1][1]);
            __half2 h3 = __floats2half2_rn(sacc[2*kc+1][2], sacc[2*kc+1][3]);
            pf[0] = *(uint32_t*)&h0; pf[1] = *(uint32_t*)&h1;
            pf[2] = *(uint32_t*)&h2; pf[3] = *(uint32_t*)&h3;

            #pragma unroll
            for (int jop = 0; jop < 4; jop++) {
                uint32_t r0, r1, r2, r3;
                const __half* vp = &Vs[bs][(kc * 16 + (mi & 1) * 8 + rr) * LKV
                                          + jop * 16 + (mi >> 1) * 8];
                uint32_t va = (uint32_t)__cvta_generic_to_shared(vp);
                asm volatile(
                    "ldmatrix.sync.aligned.m8n8.x4.trans.shared.b16 "
                    "{%0,%1,%2,%3}, [%4];"
                    : "=r"(r0), "=r"(r1), "=r"(r2), "=r"(r3) : "r"(va));
                mma16816(oacc[2 * jop],     pf, r0, r1);
                mma16816(oacc[2 * jop + 1], pf, r2, r3);
            }
        }
        __syncthreads();
    }

    // normalize + store fp16
    float inv0 = 1.0f / l0r, inv1 = 1.0f / l1r;
    __half* ob = oh + base;
    #pragma unroll
    for (int j = 0; j < 8; j++) {
        int c = j * 8 + tig * 2;
        *(__half2*)&ob[(size_t)row0 * D_ + c] =
            __floats2half2_rn(oacc[j][0] * inv0, oacc[j][1] * inv0);
        *(__half2*)&ob[(size_t)(row0 + 8) * D_ + c] =
            __floats2half2_rn(oacc[j][2] * inv1, oacc[j][3] * inv1);
    }
}

// ---------------------------------------------------------------------------

extern "C" void kernel_launch(void* const* d_in, const int* in_sizes, int n_in,
                              void* d_out, int out_size)
{
    const float* x  = (const float*)d_in[0];
    const float* wq = (const float*)d_in[1];
    const float* wk = (const float*)d_in[2];
    const float* wv = (const float*)d_in[3];
    const float* wo = (const float*)d_in[4];
    float* out = (float*)d_out;

    __half *qh, *kh, *vh, *atth, *xh, *wqh, *wkh, *wvh, *woh;
    cudaGetSymbolAddress((void**)&qh,   g_qh);
    cudaGetSymbolAddress((void**)&kh,   g_kh);
    cudaGetSymbolAddress((void**)&vh,   g_vh);
    cudaGetSymbolAddress((void**)&atth, g_atth);
    cudaGetSymbolAddress((void**)&xh,   g_xh);
    cudaGetSymbolAddress((void**)&wqh,  g_wqh);
    cudaGetSymbolAddress((void**)&wkh,  g_wkh);
    cudaGetSymbolAddress((void**)&wvh,  g_wvh);
    cudaGetSymbolAddress((void**)&woh,  g_woh);

    const int NX = NT_ * D_;          // 4M
    const int NW = D_ * D_;           // 1M
    f32_to_f16_kernel<<<NX / 1024, 256>>>(x,  xh,  NX);
    f32_to_f16_kernel<<<NW / 1024, 256>>>(wq, wqh, NW);
    f32_to_f16_kernel<<<NW / 1024, 256>>>(wk, wkh, NW);
    f32_to_f16_kernel<<<NW / 1024, 256>>>(wv, wvh, NW);
    f32_to_f16_kernel<<<NW / 1024, 256>>>(wo, woh, NW);

    // Fused QKV projection: z selects weight/output
    dim3 gq(D_ / 128, NT_ / 128, 3);  // (8, 32, 3)
    gemm_nt_f16_kernel<__half><<<gq, 256>>>(
        xh, wqh, wkh, wvh, qh, kh, vh, NT_, D_, D_);

    dim3 ga(S_ / 128, H_, B_);        // (16, 16, 2)
    attn_f16_kernel<<<ga, 256>>>(qh, kh, vh, atth);

    dim3 gg(D_ / 128, NT_ / 128, 1);  // (8, 32)
    gemm_nt_f16_kernel<float><<<gg, 256>>>(
        atth, woh, woh, woh, out, out, out, NT_, D_, D_);
}

// round 9
// speedup vs baseline: 9.0938x; 1.1582x over previous
#include <cuda_runtime.h>
#include <cuda_fp16.h>
#include <stdint.h>
#include <math.h>

#define B_   2
#define S_   2048
#define D_   1024
#define H_   16
#define DH_  64
#define NT_  (B_ * S_)          // 4096 tokens

// Scratch (allocation-free rule -> __device__ globals)
__device__ __half g_qh[NT_ * D_];
__device__ __half g_kh[NT_ * D_];
__device__ __half g_vh[NT_ * D_];
__device__ __half g_atth[NT_ * D_];
__device__ __half g_xh[NT_ * D_];
__device__ __half g_wqh[D_ * D_];
__device__ __half g_wkh[D_ * D_];
__device__ __half g_wvh[D_ * D_];
__device__ __half g_woh[D_ * D_];

__device__ __forceinline__ void mma16816(float* c, const uint32_t* a,
                                         uint32_t b0, uint32_t b1)
{
    asm volatile(
        "mma.sync.aligned.m16n8k16.row.col.f32.f16.f16.f32 "
        "{%0,%1,%2,%3}, {%4,%5,%6,%7}, {%8,%9}, {%0,%1,%2,%3};\n"
        : "+f"(c[0]), "+f"(c[1]), "+f"(c[2]), "+f"(c[3])
        : "r"(a[0]), "r"(a[1]), "r"(a[2]), "r"(a[3]), "r"(b0), "r"(b1));
}

__device__ __forceinline__ void ldsm4(uint32_t* r, const void* p)
{
    uint32_t a = (uint32_t)__cvta_generic_to_shared(p);
    asm volatile("ldmatrix.sync.aligned.m8n8.x4.shared.b16 {%0,%1,%2,%3}, [%4];"
                 : "=r"(r[0]), "=r"(r[1]), "=r"(r[2]), "=r"(r[3]) : "r"(a));
}

__device__ __forceinline__ void cp16(void* smem, const void* gmem)
{
    uint32_t sa = (uint32_t)__cvta_generic_to_shared(smem);
    asm volatile("cp.async.cg.shared.global [%0], [%1], 16;\n"
                 :: "r"(sa), "l"(gmem));
}
__device__ __forceinline__ void cp_commit()
{
    asm volatile("cp.async.commit_group;\n");
}

// ---------------------------------------------------------------------------
// Fused fp32 -> fp16 convert for x + 4 weights (8M elements total).
// 16 elements/thread, 4 independent float4 loads (MLP=4).
// Segments of 1M elements: [0..3]=x, 4=wq, 5=wk, 6=wv, 7=wo.
// ---------------------------------------------------------------------------
__global__ __launch_bounds__(256) void convert_all_kernel(
    const float* __restrict__ x,  const float* __restrict__ wq,
    const float* __restrict__ wk, const float* __restrict__ wv,
    const float* __restrict__ wo,
    __half* __restrict__ xh, __half* __restrict__ wqh,
    __half* __restrict__ wkh, __half* __restrict__ wvh,
    __half* __restrict__ woh)
{
    size_t gi = ((size_t)blockIdx.x * 256 + threadIdx.x) * 16;
    int seg = (int)(gi >> 20);
    const float* in; __half* out; size_t off;
    if (seg < 4)      { in = x;  out = xh;  off = gi; }
    else if (seg == 4){ in = wq; out = wqh; off = gi - (4u << 20); }
    else if (seg == 5){ in = wk; out = wkh; off = gi - (5u << 20); }
    else if (seg == 6){ in = wv; out = wvh; off = gi - (6u << 20); }
    else              { in = wo; out = woh; off = gi - (7u << 20); }

    float4 v0 = *(const float4*)&in[off];
    float4 v1 = *(const float4*)&in[off + 4];
    float4 v2 = *(const float4*)&in[off + 8];
    float4 v3 = *(const float4*)&in[off + 12];
    __half2 h[8];
    h[0] = __floats2half2_rn(v0.x, v0.y); h[1] = __floats2half2_rn(v0.z, v0.w);
    h[2] = __floats2half2_rn(v1.x, v1.y); h[3] = __floats2half2_rn(v1.z, v1.w);
    h[4] = __floats2half2_rn(v2.x, v2.y); h[5] = __floats2half2_rn(v2.z, v2.w);
    h[6] = __floats2half2_rn(v3.x, v3.y); h[7] = __floats2half2_rn(v3.z, v3.w);
    *(int4*)&out[off]     = *(int4*)&h[0];
    *(int4*)&out[off + 8] = *(int4*)&h[4];
}

// ---------------------------------------------------------------------------
// C[M,N] = A[M,K] @ W[N,K]^T  fp16 mma, f32 accum, OutT epilogue.
// Block 128x128, BK=32, 8 warps, warp tile 64x32.
// 3-stage cp.async ring, 1 sync/iter, ldmatrix.x4 fragments.
// blockIdx.z picks W/C pair (QKV fuse).
// ---------------------------------------------------------------------------
#define LDA 40
#define GSTG 3
#define GTILE (128 * LDA)

template <typename OutT>
__global__ __launch_bounds__(256, 2) void gemm_nt_f16_kernel(
    const __half* __restrict__ A,
    const __half* __restrict__ W0, const __half* __restrict__ W1,
    const __half* __restrict__ W2,
    OutT* __restrict__ C0, OutT* __restrict__ C1, OutT* __restrict__ C2,
    int M, int N, int K)
{
    extern __shared__ __half smem[];
    __half* As = smem;                  // [GSTG][128*LDA]
    __half* Bs = smem + GSTG * GTILE;   // [GSTG][128*LDA]

    const __half* W = (blockIdx.z == 0) ? W0 : (blockIdx.z == 1) ? W1 : W2;
    OutT*         C = (blockIdx.z == 0) ? C0 : (blockIdx.z == 1) ? C1 : C2;

    int tid  = threadIdx.x;
    int wid  = tid >> 5, lane = tid & 31;
    int gid  = lane >> 2, tig = lane & 3;
    int wm   = (wid & 1) * 64;
    int wn   = (wid >> 1) * 32;
    int m0   = blockIdx.y * 128;
    int n0   = blockIdx.x * 128;

    int lrow = tid >> 2, lq = (tid & 3) * 8;   // cp.async loader mapping

    // ldmatrix per-lane offsets (halves)
    int aoff = (wm + (lane & 15)) * LDA + (lane >> 4) * 8;
    int boff = (wn + (lane & 7) + ((lane >> 4) & 1) * 8) * LDA
             + ((lane >> 3) & 1) * 8;

    float acc[4][4][4] = {};

    const int NIT = K / 32;
    // prologue: stages 0,1
    #pragma unroll
    for (int s = 0; s < 2; s++) {
        int k0 = s * 32;
        #pragma unroll
        for (int u = 0; u < 2; u++) {
            int row = lrow + u * 64;
            cp16(&As[s * GTILE + row * LDA + lq],
                 &A[(size_t)(m0 + row) * K + k0 + lq]);
            cp16(&Bs[s * GTILE + row * LDA + lq],
                 &W[(size_t)(n0 + row) * K + k0 + lq]);
        }
        cp_commit();
    }

    int stg = 0;
    for (int t = 0; t < NIT; t++) {
        if (t + 1 < NIT) asm volatile("cp.async.wait_group 1;\n");
        else             asm volatile("cp.async.wait_group 0;\n");
        __syncthreads();

        if (t + 2 < NIT) {
            int ps = (t + 2) % GSTG;
            int k0 = (t + 2) * 32;
            #pragma unroll
            for (int u = 0; u < 2; u++) {
                int row = lrow + u * 64;
                cp16(&As[ps * GTILE + row * LDA + lq],
                     &A[(size_t)(m0 + row) * K + k0 + lq]);
                cp16(&Bs[ps * GTILE + row * LDA + lq],
                     &W[(size_t)(n0 + row) * K + k0 + lq]);
            }
            cp_commit();
        }

        const __half* as = &As[stg * GTILE];
        const __half* bs = &Bs[stg * GTILE];
        #pragma unroll
        for (int ks = 0; ks < 2; ks++) {
            int kb = ks * 16;
            uint32_t af[4][4], bf[2][4];
            #pragma unroll
            for (int i = 0; i < 4; i++)
                ldsm4(af[i], as + aoff + i * 16 * LDA + kb);
            #pragma unroll
            for (int jp = 0; jp < 2; jp++)
                ldsm4(bf[jp], bs + boff + jp * 16 * LDA + kb);
            #pragma unroll
            for (int i = 0; i < 4; i++) {
                mma16816(acc[i][0], af[i], bf[0][0], bf[0][1]);
                mma16816(acc[i][1], af[i], bf[0][2], bf[0][3]);
                mma16816(acc[i][2], af[i], bf[1][0], bf[1][1]);
                mma16816(acc[i][3], af[i], bf[1][2], bf[1][3]);
            }
        }
        stg = (stg + 1) % GSTG;
    }

    #pragma unroll
    for (int i = 0; i < 4; i++)
        #pragma unroll
        for (int j = 0; j < 4; j++) {
            int r = m0 + wm + i * 16 + gid;
            int c = n0 + wn + j * 8 + tig * 2;
            if (sizeof(OutT) == 2) {
                *(__half2*)((__half*)C + (size_t)r * N + c) =
                    __floats2half2_rn(acc[i][j][0], acc[i][j][1]);
                *(__half2*)((__half*)C + (size_t)(r + 8) * N + c) =
                    __floats2half2_rn(acc[i][j][2], acc[i][j][3]);
            } else {
                float2 lo = {acc[i][j][0], acc[i][j][1]};
                float2 hi = {acc[i][j][2], acc[i][j][3]};
                *(float2*)((float*)C + (size_t)r * N + c)       = lo;
                *(float2*)((float*)C + (size_t)(r + 8) * N + c) = hi;
            }
        }
}

// ---------------------------------------------------------------------------
// Causal flash attention, fp16 tensor cores (FA2 register-resident),
// 2-stage cp.async KV pipeline. Heavy q-tiles launched first.
// ---------------------------------------------------------------------------
#define LKV 72

__global__ __launch_bounds__(256, 2) void attn_f16_kernel(
    const __half* __restrict__ qh, const __half* __restrict__ kh,
    const __half* __restrict__ vh, __half* __restrict__ oh)
{
    __shared__ __half Ks[2][64 * LKV];
    __shared__ __half Vs[2][64 * LKV];

    int tid = threadIdx.x, wid = tid >> 5, lane = tid & 31;
    int gid = lane >> 2, tig = lane & 3;
    int q0 = (gridDim.x - 1 - blockIdx.x) * 128;   // heavy blocks first
    int h  = blockIdx.y, b = blockIdx.z;
    size_t base = ((size_t)b * S_) * D_ + h * DH_;
    int wrow = wid * 16;
    int row0 = q0 + wrow + gid;

    const __half* qb = qh + base;
    const __half* kb = kh + base;
    const __half* vb = vh + base;

    int lrow = tid >> 3, loff = (tid & 7) * 8;

    uint32_t qf[4][4];
    #pragma unroll
    for (int kc = 0; kc < 4; kc++) {
        const __half* p0 = &qb[(size_t)row0 * D_ + kc * 16 + tig * 2];
        const __half* p1 = &qb[(size_t)(row0 + 8) * D_ + kc * 16 + tig * 2];
        qf[kc][0] = *(const uint32_t*)(p0);
        qf[kc][1] = *(const uint32_t*)(p1);
        qf[kc][2] = *(const uint32_t*)(p0 + 8);
        qf[kc][3] = *(const uint32_t*)(p1 + 8);
    }

    float m0r = -1e30f, m1r = -1e30f, l0r = 0.0f, l1r = 0.0f;
    float oacc[8][4] = {};
    const float scale = 0.125f;

    int ntiles = (q0 >> 6) + 2;

    #pragma unroll
    for (int u = 0; u < 2; u++) {
        int row = lrow + u * 32;
        cp16(&Ks[0][row * LKV + loff], &kb[(size_t)row * D_ + loff]);
        cp16(&Vs[0][row * LKV + loff], &vb[(size_t)row * D_ + loff]);
    }
    cp_commit();

    for (int kt = 0; kt < ntiles; kt++) {
        int kv0 = kt * 64;
        int bs = kt & 1;
        if (kt + 1 < ntiles) {
            int nv0 = kv0 + 64;
            #pragma unroll
            for (int u = 0; u < 2; u++) {
                int row = lrow + u * 32;
                cp16(&Ks[bs ^ 1][row * LKV + loff],
                     &kb[(size_t)(nv0 + row) * D_ + loff]);
                cp16(&Vs[bs ^ 1][row * LKV + loff],
                     &vb[(size_t)(nv0 + row) * D_ + loff]);
            }
            cp_commit();
            asm volatile("cp.async.wait_group 1;\n");
        } else {
            asm volatile("cp.async.wait_group 0;\n");
        }
        __syncthreads();

        float sacc[8][4] = {};
        #pragma unroll
        for (int kc = 0; kc < 4; kc++)
            #pragma unroll
            for (int j = 0; j < 8; j++) {
                const __half* bp = &Ks[bs][(j * 8 + gid) * LKV + kc * 16 + tig * 2];
                mma16816(sacc[j], qf[kc],
                         *(const uint32_t*)(bp), *(const uint32_t*)(bp + 8));
            }

        bool need_mask = (kv0 + 63 > q0 + wrow);
        #pragma unroll
        for (int j = 0; j < 8; j++) {
            int c0 = kv0 + j * 8 + tig * 2;
            #pragma unroll
            for (int u = 0; u < 4; u++) sacc[j][u] *= scale;
            if (need_mask) {
                if (c0     > row0)     sacc[j][0] = -1e30f;
                if (c0 + 1 > row0)     sacc[j][1] = -1e30f;
                if (c0     > row0 + 8) sacc[j][2] = -1e30f;
                if (c0 + 1 > row0 + 8) sacc[j][3] = -1e30f;
            }
        }

        float rm0 = -1e30f, rm1 = -1e30f;
        #pragma unroll
        for (int j = 0; j < 8; j++) {
            rm0 = fmaxf(rm0, fmaxf(sacc[j][0], sacc[j][1]));
            rm1 = fmaxf(rm1, fmaxf(sacc[j][2], sacc[j][3]));
        }
        rm0 = fmaxf(rm0, __shfl_xor_sync(0xffffffffu, rm0, 1));
        rm0 = fmaxf(rm0, __shfl_xor_sync(0xffffffffu, rm0, 2));
        rm1 = fmaxf(rm1, __shfl_xor_sync(0xffffffffu, rm1, 1));
        rm1 = fmaxf(rm1, __shfl_xor_sync(0xffffffffu, rm1, 2));
        float nm0 = fmaxf(m0r, rm0), nm1 = fmaxf(m1r, rm1);
        float corr0 = __expf(m0r - nm0), corr1 = __expf(m1r - nm1);
        m0r = nm0; m1r = nm1;

        float sum0 = 0.0f, sum1 = 0.0f;
        #pragma unroll
        for (int j = 0; j < 8; j++) {
            sacc[j][0] = __expf(sacc[j][0] - nm0);
            sacc[j][1] = __expf(sacc[j][1] - nm0);
            sacc[j][2] = __expf(sacc[j][2] - nm1);
            sacc[j][3] = __expf(sacc[j][3] - nm1);
            sum0 += sacc[j][0] + sacc[j][1];
            sum1 += sacc[j][2] + sacc[j][3];
        }
        sum0 += __shfl_xor_sync(0xffffffffu, sum0, 1);
        sum0 += __shfl_xor_sync(0xffffffffu, sum0, 2);
        sum1 += __shfl_xor_sync(0xffffffffu, sum1, 1);
        sum1 += __shfl_xor_sync(0xffffffffu, sum1, 2);
        l0r = l0r * corr0 + sum0;
        l1r = l1r * corr1 + sum1;

        #pragma unroll
        for (int j = 0; j < 8; j++) {
            oacc[j][0] *= corr0; oacc[j][1] *= corr0;
            oacc[j][2] *= corr1; oacc[j][3] *= corr1;
        }

        int mi = lane >> 3, rr = lane & 7;
        #pragma unroll
        for (int kc = 0; kc < 4; kc++) {
            uint32_t pf[4];
            __half2 h0 = __floats2half2_rn(sacc[2*kc][0],   sacc[2*kc][1]);
            __half2 h1 = __floats2half2_rn(sacc[2*kc][2],   sacc[2*kc][3]);
            __half2 h2 = __floats2half2_rn(sacc[2*kc+1][0], sacc[2*kc+1][1]);
            __half2 h3 = __floats2half2_rn(sacc[2*kc+1][2], sacc[2*kc+1][3]);
            pf[0] = *(uint32_t*)&h0; pf[1] = *(uint32_t*)&h1;
            pf[2] = *(uint32_t*)&h2; pf[3] = *(uint32_t*)&h3;

            #pragma unroll
            for (int jop = 0; jop < 4; jop++) {
                uint32_t r0, r1, r2, r3;
                const __half* vp = &Vs[bs][(kc * 16 + (mi & 1) * 8 + rr) * LKV
                                          + jop * 16 + (mi >> 1) * 8];
                uint32_t va = (uint32_t)__cvta_generic_to_shared(vp);
                asm volatile(
                    "ldmatrix.sync.aligned.m8n8.x4.trans.shared.b16 "
                    "{%0,%1,%2,%3}, [%4];"
                    : "=r"(r0), "=r"(r1), "=r"(r2), "=r"(r3) : "r"(va));
                mma16816(oacc[2 * jop],     pf, r0, r1);
                mma16816(oacc[2 * jop + 1], pf, r2, r3);
            }
        }
        __syncthreads();
    }

    float inv0 = 1.0f / l0r, inv1 = 1.0f / l1r;
    __half* ob = oh + base;
    #pragma unroll
    for (int j = 0; j < 8; j++) {
        int c = j * 8 + tig * 2;
        *(__half2*)&ob[(size_t)row0 * D_ + c] =
            __floats2half2_rn(oacc[j][0] * inv0, oacc[j][1] * inv0);
        *(__half2*)&ob[(size_t)(row0 + 8) * D_ + c] =
            __floats2half2_rn(oacc[j][2] * inv1, oacc[j][3] * inv1);
    }
}

// ---------------------------------------------------------------------------

extern "C" void kernel_launch(void* const* d_in, const int* in_sizes, int n_in,
                              void* d_out, int out_size)
{
    const float* x  = (const float*)d_in[0];
    const float* wq = (const float*)d_in[1];
    const float* wk = (const float*)d_in[2];
    const float* wv = (const float*)d_in[3];
    const float* wo = (const float*)d_in[4];
    float* out = (float*)d_out;

    __half *qh, *kh, *vh, *atth, *xh, *wqh, *wkh, *wvh, *woh;
    cudaGetSymbolAddress((void**)&qh,   g_qh);
    cudaGetSymbolAddress((void**)&kh,   g_kh);
    cudaGetSymbolAddress((void**)&vh,   g_vh);
    cudaGetSymbolAddress((void**)&atth, g_atth);
    cudaGetSymbolAddress((void**)&xh,   g_xh);
    cudaGetSymbolAddress((void**)&wqh,  g_wqh);
    cudaGetSymbolAddress((void**)&wkh,  g_wkh);
    cudaGetSymbolAddress((void**)&wvh,  g_wvh);
    cudaGetSymbolAddress((void**)&woh,  g_woh);

    // One fused convert: 8M elements, 16/thread
    convert_all_kernel<<<2048, 256>>>(x, wq, wk, wv, wo,
                                      xh, wqh, wkh, wvh, woh);

    const int gsmem = GSTG * GTILE * 2 * (int)sizeof(__half);  // 61440
    cudaFuncSetAttribute(gemm_nt_f16_kernel<__half>,
                         cudaFuncAttributeMaxDynamicSharedMemorySize, gsmem);
    cudaFuncSetAttribute(gemm_nt_f16_kernel<float>,
                         cudaFuncAttributeMaxDynamicSharedMemorySize, gsmem);

    // Fused QKV projection: z selects weight/output
    dim3 gq(D_ / 128, NT_ / 128, 3);  // (8, 32, 3)
    gemm_nt_f16_kernel<__half><<<gq, 256, gsmem>>>(
        xh, wqh, wkh, wvh, qh, kh, vh, NT_, D_, D_);

    dim3 ga(S_ / 128, H_, B_);        // (16, 16, 2)
    attn_f16_kernel<<<ga, 256>>>(qh, kh, vh, atth);

    dim3 gg(D_ / 128, NT_ / 128, 1);  // (8, 32)
    gemm_nt_f16_kernel<float><<<gg, 256, gsmem>>>(
        atth, woh, woh, woh, out, out, out, NT_, D_, D_);
}

// round 12
// speedup vs baseline: 9.3494x; 1.0281x over previous
#include <cuda_runtime.h>
#include <cuda_fp16.h>
#include <stdint.h>
#include <math.h>

#define B_   2
#define S_   2048
#define D_   1024
#define H_   16
#define DH_  64
#define NT_  (B_ * S_)          // 4096 tokens

// Scratch (allocation-free rule -> __device__ globals)
__device__ __half g_qh[NT_ * D_];
__device__ __half g_kh[NT_ * D_];
__device__ __half g_vh[NT_ * D_];
__device__ __half g_atth[NT_ * D_];
__device__ __half g_xh[NT_ * D_];
__device__ __half g_wqh[D_ * D_];
__device__ __half g_wkh[D_ * D_];
__device__ __half g_wvh[D_ * D_];
__device__ __half g_woh[D_ * D_];

__device__ __forceinline__ void mma16816(float* c, const uint32_t* a,
                                         uint32_t b0, uint32_t b1)
{
    asm volatile(
        "mma.sync.aligned.m16n8k16.row.col.f32.f16.f16.f32 "
        "{%0,%1,%2,%3}, {%4,%5,%6,%7}, {%8,%9}, {%0,%1,%2,%3};\n"
        : "+f"(c[0]), "+f"(c[1]), "+f"(c[2]), "+f"(c[3])
        : "r"(a[0]), "r"(a[1]), "r"(a[2]), "r"(a[3]), "r"(b0), "r"(b1));
}

__device__ __forceinline__ void ldsm4(uint32_t* r, const void* p)
{
    uint32_t a = (uint32_t)__cvta_generic_to_shared(p);
    asm volatile("ldmatrix.sync.aligned.m8n8.x4.shared.b16 {%0,%1,%2,%3}, [%4];"
                 : "=r"(r[0]), "=r"(r[1]), "=r"(r[2]), "=r"(r[3]) : "r"(a));
}

__device__ __forceinline__ void cp16(void* smem, const void* gmem)
{
    uint32_t sa = (uint32_t)__cvta_generic_to_shared(smem);
    asm volatile("cp.async.cg.shared.global [%0], [%1], 16;\n"
                 :: "r"(sa), "l"(gmem));
}
__device__ __forceinline__ void cp_commit()
{
    asm volatile("cp.async.commit_group;\n");
}

// ---------------------------------------------------------------------------
// Fused fp32 -> fp16 convert for x + 4 weights (8M elements total).
// ---------------------------------------------------------------------------
__global__ __launch_bounds__(256) void convert_all_kernel(
    const float* __restrict__ x,  const float* __restrict__ wq,
    const float* __restrict__ wk, const float* __restrict__ wv,
    const float* __restrict__ wo,
    __half* __restrict__ xh, __half* __restrict__ wqh,
    __half* __restrict__ wkh, __half* __restrict__ wvh,
    __half* __restrict__ woh)
{
    size_t gi = ((size_t)blockIdx.x * 256 + threadIdx.x) * 16;
    int seg = (int)(gi >> 20);
    const float* in; __half* out; size_t off;
    if (seg < 4)      { in = x;  out = xh;  off = gi; }
    else if (seg == 4){ in = wq; out = wqh; off = gi - (4u << 20); }
    else if (seg == 5){ in = wk; out = wkh; off = gi - (5u << 20); }
    else if (seg == 6){ in = wv; out = wvh; off = gi - (6u << 20); }
    else              { in = wo; out = woh; off = gi - (7u << 20); }

    float4 v0 = *(const float4*)&in[off];
    float4 v1 = *(const float4*)&in[off + 4];
    float4 v2 = *(const float4*)&in[off + 8];
    float4 v3 = *(const float4*)&in[off + 12];
    __half2 h[8];
    h[0] = __floats2half2_rn(v0.x, v0.y); h[1] = __floats2half2_rn(v0.z, v0.w);
    h[2] = __floats2half2_rn(v1.x, v1.y); h[3] = __floats2half2_rn(v1.z, v1.w);
    h[4] = __floats2half2_rn(v2.x, v2.y); h[5] = __floats2half2_rn(v2.z, v2.w);
    h[6] = __floats2half2_rn(v3.x, v3.y); h[7] = __floats2half2_rn(v3.z, v3.w);
    *(int4*)&out[off]     = *(int4*)&h[0];
    *(int4*)&out[off + 8] = *(int4*)&h[4];
}

// ---------------------------------------------------------------------------
// C[M,N] = A[M,K] @ W[N,K]^T  fp16 mma, f32 accum, OutT epilogue.
// Block 128x128, BK=64, 4 warps (2x2), warp tile 64x64 (4x8 mma grid).
// 2-stage cp.async pipeline, pitch 72 halves (conflict-free ldmatrix).
// blockIdx.z picks W/C pair (QKV fuse).
// ---------------------------------------------------------------------------
#define LDG2 72                      // pitch in halves (144 B)
#define GT2  (128 * LDG2)            // halves per operand tile
#define GSM2 (2 * 2 * GT2 * 2)       // bytes: 2 stages x (A+B) x 2B = 73728

template <typename OutT>
__global__ __launch_bounds__(128, 2) void gemm_nt_f16_kernel(
    const __half* __restrict__ A,
    const __half* __restrict__ W0, const __half* __restrict__ W1,
    const __half* __restrict__ W2,
    OutT* __restrict__ C0, OutT* __restrict__ C1, OutT* __restrict__ C2,
    int M, int N, int K)
{
    extern __shared__ __half smem[];
    // layout: [stage][A tile GT2][B tile GT2]
    const __half* W = (blockIdx.z == 0) ? W0 : (blockIdx.z == 1) ? W1 : W2;
    OutT*         C = (blockIdx.z == 0) ? C0 : (blockIdx.z == 1) ? C1 : C2;

    int tid  = threadIdx.x;
    int wid  = tid >> 5, lane = tid & 31;
    int gid  = lane >> 2, tig = lane & 3;
    int wm   = (wid & 1) * 64;
    int wn   = (wid >> 1) * 64;
    int m0   = blockIdx.y * 128;
    int n0   = blockIdx.x * 128;

    // ldmatrix per-lane base offsets (halves)
    int aoff = (wm + (lane & 15)) * LDG2 + (lane >> 4) * 8;
    int boff = (wn + (lane & 7) + ((lane >> 4) & 1) * 8) * LDG2
             + ((lane >> 3) & 1) * 8;

    float acc[4][8][4] = {};

    const int NIT = K / 64;

    // loader: thread covers 8 A-chunks + 8 B-chunks of 16B per stage
    auto load_stage = [&](int slot, int k0) {
        __half* as = smem + slot * 2 * GT2;
        __half* bs = as + GT2;
        #pragma unroll
        for (int u = 0; u < 8; u++) {
            int c = tid + u * 128;              // 0..1023
            int row = c >> 3, col = (c & 7) * 8;
            cp16(&as[row * LDG2 + col], &A[(size_t)(m0 + row) * K + k0 + col]);
            cp16(&bs[row * LDG2 + col], &W[(size_t)(n0 + row) * K + k0 + col]);
        }
        cp_commit();
    };

    load_stage(0, 0);
    load_stage(1, 64);

    for (int t = 0; t < NIT; t++) {
        if (t + 1 < NIT) asm volatile("cp.async.wait_group 1;\n");
        else             asm volatile("cp.async.wait_group 0;\n");
        __syncthreads();

        const __half* as = smem + (t & 1) * 2 * GT2;
        const __half* bs = as + GT2;

        #pragma unroll
        for (int ks = 0; ks < 4; ks++) {
            int kb = ks * 16;
            uint32_t af[4][4], bf[4][4];
            #pragma unroll
            for (int i = 0; i < 4; i++)
                ldsm4(af[i], as + aoff + i * 16 * LDG2 + kb);
            #pragma unroll
            for (int jp = 0; jp < 4; jp++)
                ldsm4(bf[jp], bs + boff + jp * 16 * LDG2 + kb);
            #pragma unroll
            for (int i = 0; i < 4; i++)
                #pragma unroll
                for (int jp = 0; jp < 4; jp++) {
                    mma16816(acc[i][2 * jp],     af[i], bf[jp][0], bf[jp][1]);
                    mma16816(acc[i][2 * jp + 1], af[i], bf[jp][2], bf[jp][3]);
                }
        }
        __syncthreads();
        if (t + 2 < NIT) load_stage(t & 1, (t + 2) * 64);
    }

    #pragma unroll
    for (int i = 0; i < 4; i++)
        #pragma unroll
        for (int j = 0; j < 8; j++) {
            int r = m0 + wm + i * 16 + gid;
            int c = n0 + wn + j * 8 + tig * 2;
            if (sizeof(OutT) == 2) {
                *(__half2*)((__half*)C + (size_t)r * N + c) =
                    __floats2half2_rn(acc[i][j][0], acc[i][j][1]);
                *(__half2*)((__half*)C + (size_t)(r + 8) * N + c) =
                    __floats2half2_rn(acc[i][j][2], acc[i][j][3]);
            } else {
                float2 lo = {acc[i][j][0], acc[i][j][1]};
                float2 hi = {acc[i][j][2], acc[i][j][3]};
                *(float2*)((float*)C + (size_t)r * N + c)       = lo;
                *(float2*)((float*)C + (size_t)(r + 8) * N + c) = hi;
            }
        }
}

// ---------------------------------------------------------------------------
// Causal flash attention, fp16 tensor cores (FA2 register-resident),
// 2-stage cp.async KV pipeline. Heavy q-tiles launched first.
// ---------------------------------------------------------------------------
#define LKV 72

__global__ __launch_bounds__(256, 2) void attn_f16_kernel(
    const __half* __restrict__ qh, const __half* __restrict__ kh,
    const __half* __restrict__ vh, __half* __restrict__ oh)
{
    __shared__ __half Ks[2][64 * LKV];
    __shared__ __half Vs[2][64 * LKV];

    int tid = threadIdx.x, wid = tid >> 5, lane = tid & 31;
    int gid = lane >> 2, tig = lane & 3;
    int q0 = (gridDim.x - 1 - blockIdx.x) * 128;
    int h  = blockIdx.y, b = blockIdx.z;
    size_t base = ((size_t)b * S_) * D_ + h * DH_;
    int wrow = wid * 16;
    int row0 = q0 + wrow + gid;

    const __half* qb = qh + base;
    const __half* kb = kh + base;
    const __half* vb = vh + base;

    int lrow = tid >> 3, loff = (tid & 7) * 8;

    uint32_t qf[4][4];
    #pragma unroll
    for (int kc = 0; kc < 4; kc++) {
        const __half* p0 = &qb[(size_t)row0 * D_ + kc * 16 + tig * 2];
        const __half* p1 = &qb[(size_t)(row0 + 8) * D_ + kc * 16 + tig * 2];
        qf[kc][0] = *(const uint32_t*)(p0);
        qf[kc][1] = *(const uint32_t*)(p1);
        qf[kc][2] = *(const uint32_t*)(p0 + 8);
        qf[kc][3] = *(const uint32_t*)(p1 + 8);
    }

    float m0r = -1e30f, m1r = -1e30f, l0r = 0.0f, l1r = 0.0f;
    float oacc[8][4] = {};
    const float scale = 0.125f;

    int ntiles = (q0 >> 6) + 2;

    #pragma unroll
    for (int u = 0; u < 2; u++) {
        int row = lrow + u * 32;
        cp16(&Ks[0][row * LKV + loff], &kb[(size_t)row * D_ + loff]);
        cp16(&Vs[0][row * LKV + loff], &vb[(size_t)row * D_ + loff]);
    }
    cp_commit();

    for (int kt = 0; kt < ntiles; kt++) {
        int kv0 = kt * 64;
        int bs = kt & 1;
        if (kt + 1 < ntiles) {
            int nv0 = kv0 + 64;
            #pragma unroll
            for (int u = 0; u < 2; u++) {
                int row = lrow + u * 32;
                cp16(&Ks[bs ^ 1][row * LKV + loff],
                     &kb[(size_t)(nv0 + row) * D_ + loff]);
                cp16(&Vs[bs ^ 1][row * LKV + loff],
                     &vb[(size_t)(nv0 + row) * D_ + loff]);
            }
            cp_commit();
            asm volatile("cp.async.wait_group 1;\n");
        } else {
            asm volatile("cp.async.wait_group 0;\n");
        }
        __syncthreads();

        float sacc[8][4] = {};
        #pragma unroll
        for (int kc = 0; kc < 4; kc++)
            #pragma unroll
            for (int j = 0; j < 8; j++) {
                const __half* bp = &Ks[bs][(j * 8 + gid) * LKV + kc * 16 + tig * 2];
                mma16816(sacc[j], qf[kc],
                         *(const uint32_t*)(bp), *(const uint32_t*)(bp + 8));
            }

        bool need_mask = (kv0 + 63 > q0 + wrow);
        #pragma unroll
        for (int j = 0; j < 8; j++) {
            int c0 = kv0 + j * 8 + tig * 2;
            #pragma unroll
            for (int u = 0; u < 4; u++) sacc[j][u] *= scale;
            if (need_mask) {
                if (c0     > row0)     sacc[j][0] = -1e30f;
                if (c0 + 1 > row0)     sacc[j][1] = -1e30f;
                if (c0     > row0 + 8) sacc[j][2] = -1e30f;
                if (c0 + 1 > row0 + 8) sacc[j][3] = -1e30f;
            }
        }

        float rm0 = -1e30f, rm1 = -1e30f;
        #pragma unroll
        for (int j = 0; j < 8; j++) {
            rm0 = fmaxf(rm0, fmaxf(sacc[j][0], sacc[j][1]));
            rm1 = fmaxf(rm1, fmaxf(sacc[j][2], sacc[j][3]));
        }
        rm0 = fmaxf(rm0, __shfl_xor_sync(0xffffffffu, rm0, 1));
        rm0 = fmaxf(rm0, __shfl_xor_sync(0xffffffffu, rm0, 2));
        rm1 = fmaxf(rm1, __shfl_xor_sync(0xffffffffu, rm1, 1));
        rm1 = fmaxf(rm1, __shfl_xor_sync(0xffffffffu, rm1, 2));
        float nm0 = fmaxf(m0r, rm0), nm1 = fmaxf(m1r, rm1);
        float corr0 = __expf(m0r - nm0), corr1 = __expf(m1r - nm1);
        m0r = nm0; m1r = nm1;

        float sum0 = 0.0f, sum1 = 0.0f;
        #pragma unroll
        for (int j = 0; j < 8; j++) {
            sacc[j][0] = __expf(sacc[j][0] - nm0);
            sacc[j][1] = __expf(sacc[j][1] - nm0);
            sacc[j][2] = __expf(sacc[j][2] - nm1);
            sacc[j][3] = __expf(sacc[j][3] - nm1);
            sum0 += sacc[j][0] + sacc[j][1];
            sum1 += sacc[j][2] + sacc[j][3];
        }
        sum0 += __shfl_xor_sync(0xffffffffu, sum0, 1);
        sum0 += __shfl_xor_sync(0xffffffffu, sum0, 2);
        sum1 += __shfl_xor_sync(0xffffffffu, sum1, 1);
        sum1 += __shfl_xor_sync(0xffffffffu, sum1, 2);
        l0r = l0r * corr0 + sum0;
        l1r = l1r * corr1 + sum1;

        #pragma unroll
        for (int j = 0; j < 8; j++) {
            oacc[j][0] *= corr0; oacc[j][1] *= corr0;
            oacc[j][2] *= corr1; oacc[j][3] *= corr1;
        }

        int mi = lane >> 3, rr = lane & 7;
        #pragma unroll
        for (int kc = 0; kc < 4; kc++) {
            uint32_t pf[4];
            __half2 h0 = __floats2half2_rn(sacc[2*kc][0],   sacc[2*kc][1]);
            __half2 h1 = __floats2half2_rn(sacc[2*kc][2],   sacc[2*kc][3]);
            __half2 h2 = __floats2half2_rn(sacc[2*kc+1][0], sacc[2*kc+1][1]);
            __half2 h3 = __floats2half2_rn(sacc[2*kc+1][2], sacc[2*kc+1][3]);
            pf[0] = *(uint32_t*)&h0; pf[1] = *(uint32_t*)&h1;
            pf[2] = *(uint32_t*)&h2; pf[3] = *(uint32_t*)&h3;

            #pragma unroll
            for (int jop = 0; jop < 4; jop++) {
                uint32_t r0, r1, r2, r3;
                const __half* vp = &Vs[bs][(kc * 16 + (mi & 1) * 8 + rr) * LKV
                                          + jop * 16 + (mi >> 1) * 8];
                uint32_t va = (uint32_t)__cvta_generic_to_shared(vp);
                asm volatile(
                    "ldmatrix.sync.aligned.m8n8.x4.trans.shared.b16 "
                    "{%0,%1,%2,%3}, [%4];"
                    : "=r"(r0), "=r"(r1), "=r"(r2), "=r"(r3) : "r"(va));
                mma16816(oacc[2 * jop],     pf, r0, r1);
                mma16816(oacc[2 * jop + 1], pf, r2, r3);
            }
        }
        __syncthreads();
    }

    float inv0 = 1.0f / l0r, inv1 = 1.0f / l1r;
    __half* ob = oh + base;
    #pragma unroll
    for (int j = 0; j < 8; j++) {
        int c = j * 8 + tig * 2;
        *(__half2*)&ob[(size_t)row0 * D_ + c] =
            __floats2half2_rn(oacc[j][0] * inv0, oacc[j][1] * inv0);
        *(__half2*)&ob[(size_t)(row0 + 8) * D_ + c] =
            __floats2half2_rn(oacc[j][2] * inv1, oacc[j][3] * inv1);
    }
}

// ---------------------------------------------------------------------------

extern "C" void kernel_launch(void* const* d_in, const int* in_sizes, int n_in,
                              void* d_out, int out_size)
{
    const float* x  = (const float*)d_in[0];
    const float* wq = (const float*)d_in[1];
    const float* wk = (const float*)d_in[2];
    const float* wv = (const float*)d_in[3];
    const float* wo = (const float*)d_in[4];
    float* out = (float*)d_out;

    __half *qh, *kh, *vh, *atth, *xh, *wqh, *wkh, *wvh, *woh;
    cudaGetSymbolAddress((void**)&qh,   g_qh);
    cudaGetSymbolAddress((void**)&kh,   g_kh);
    cudaGetSymbolAddress((void**)&vh,   g_vh);
    cudaGetSymbolAddress((void**)&atth, g_atth);
    cudaGetSymbolAddress((void**)&xh,   g_xh);
    cudaGetSymbolAddress((void**)&wqh,  g_wqh);
    cudaGetSymbolAddress((void**)&wkh,  g_wkh);
    cudaGetSymbolAddress((void**)&wvh,  g_wvh);
    cudaGetSymbolAddress((void**)&woh,  g_woh);

    convert_all_kernel<<<2048, 256>>>(x, wq, wk, wv, wo,
                                      xh, wqh, wkh, wvh, woh);

    cudaFuncSetAttribute(gemm_nt_f16_kernel<__half>,
                         cudaFuncAttributeMaxDynamicSharedMemorySize, GSM2);
    cudaFuncSetAttribute(gemm_nt_f16_kernel<float>,
                         cudaFuncAttributeMaxDynamicSharedMemorySize, GSM2);

    // Fused QKV projection: z selects weight/output
    dim3 gq(D_ / 128, NT_ / 128, 3);  // (8, 32, 3)
    gemm_nt_f16_kernel<__half><<<gq, 128, GSM2>>>(
        xh, wqh, wkh, wvh, qh, kh, vh, NT_, D_, D_);

    dim3 ga(S_ / 128, H_, B_);        // (16, 16, 2)
    attn_f16_kernel<<<ga, 256>>>(qh, kh, vh, atth);

    dim3 gg(D_ / 128, NT_ / 128, 1);
    gemm_nt_f16_kernel<float><<<gg, 128, GSM2>>>(
        atth, woh, woh, woh, out, out, out, NT_, D_, D_);
}